// round 8
// baseline (speedup 1.0000x reference)
#include <cuda_runtime.h>

#define S_LEN   2048
#define B_SZ    2
#define DM      1024
#define NH      16
#define HD      64
#define HK      1024            // NH*HD
#define MROWS   (B_SZ*S_LEN)    // 4096

// ---------------- scratch (static device arrays; no allocation) -------------
__device__ float g_q[B_SZ*NH*S_LEN*HD];   // (b,h,s,k)
__device__ float g_k[B_SZ*NH*S_LEN*HD];
__device__ float g_v[B_SZ*NH*S_LEN*HD];
__device__ float g_o[MROWS*HK];           // (b,s,hk), tf32-rounded at attn epi
__device__ float g_xr[MROWS*DM];          // tf32-rounded x
__device__ float g_wq[DM*HK], g_wk[DM*HK], g_wv[DM*HK], g_wo[HK*DM];

// ---------------- helpers ----------------------------------------------------
__device__ __forceinline__ unsigned f2tf32(float f) {
    unsigned r;
    asm("cvt.rna.tf32.f32 %0, %1;" : "=r"(r) : "f"(f));
    return r;
}
__device__ __forceinline__ float f2tf32f(float f) {
    float r;
    asm("cvt.rna.tf32.f32 %0, %1;" : "=f"(r) : "f"(f));
    return r;
}

__device__ __forceinline__ void mma_tf32(float* c, const unsigned* a, const unsigned* b) {
    asm volatile(
        "mma.sync.aligned.m16n8k8.row.col.f32.tf32.tf32.f32 "
        "{%0,%1,%2,%3}, {%4,%5,%6,%7}, {%8,%9}, {%0,%1,%2,%3};\n"
        : "+f"(c[0]), "+f"(c[1]), "+f"(c[2]), "+f"(c[3])
        : "r"(a[0]), "r"(a[1]), "r"(a[2]), "r"(a[3]),
          "r"(b[0]), "r"(b[1]));
}

__device__ __forceinline__ void cp16(unsigned dst, const float* src) {
    asm volatile("cp.async.cg.shared.global [%0], [%1], 16;" :: "r"(dst), "l"(src));
}

// ---------------- pre-round kernel (f32 -> tf32-rounded f32) -----------------
__global__ void round_pre(const float* __restrict__ src, float* __restrict__ dst, int n4)
{
    int i = blockIdx.x * 256 + threadIdx.x;
    if (i < n4) {
        float4 v = ((const float4*)src)[i];
        v.x = f2tf32f(v.x); v.y = f2tf32f(v.y);
        v.z = f2tf32f(v.z); v.w = f2tf32f(v.w);
        ((float4*)dst)[i] = v;
    }
}

// =====================================================================
// TF32 GEMM: CTA 128x128, warp tile 64x64 (4 warps), K-chunk 32,
// cp.async staging (inputs pre-rounded), ldmatrix A-frags, double buffer.
// =====================================================================
#define ASTR 36
#define BSTR 136
#define ABUFB (128*ASTR*4)
#define BBUFB (32*BSTR*4)
#define GEMM_SMEM (2*ABUFB + 2*BBUFB)   // 71680 B

#define G_STAGE(buf, kk) do {                                                 \
    _Pragma("unroll")                                                         \
    for (int it = 0; it < 8; it++) {                                          \
        int la = it*128 + tid;                                                \
        int r = la >> 3, c = la & 7;                                          \
        cp16(asA + (buf)*ABUFB + (unsigned)((r*ASTR + c*4)*4),                \
             aP + (size_t)r*KROW + (kk) + c*4);                               \
        int rb = la >> 5, cb = la & 31;                                       \
        cp16(asB + (buf)*BBUFB + (unsigned)((rb*BSTR + cb*4)*4),              \
             bP + (size_t)((kk) + rb)*NROW + cb*4);                           \
    }                                                                         \
    asm volatile("cp.async.commit_group;");                                   \
} while (0)

#define G_MMA(buf) do {                                                       \
    const float* Bp = BsF + (buf)*(32*BSTR);                                  \
    unsigned aBase = asA + (buf)*ABUFB;                                       \
    _Pragma("unroll")                                                         \
    for (int kb = 0; kb < 32; kb += 8) {                                      \
        unsigned af[4][4], bf[8][2];                                          \
        _Pragma("unroll")                                                     \
        for (int i = 0; i < 4; i++) {                                         \
            unsigned ad = aBase +                                             \
                (unsigned)(((wm*64 + i*16 + laneRow)*ASTR + kb + laneCol)*4); \
            asm volatile(                                                     \
                "ldmatrix.sync.aligned.m8n8.x4.shared.b16 {%0,%1,%2,%3}, [%4];" \
                : "=r"(af[i][0]), "=r"(af[i][1]), "=r"(af[i][2]), "=r"(af[i][3]) \
                : "r"(ad));                                                   \
        }                                                                     \
        _Pragma("unroll")                                                     \
        for (int j = 0; j < 8; j++) {                                         \
            int nb = wn*64 + j*8;                                             \
            bf[j][0] = __float_as_uint(Bp[(kb+tig)*BSTR + nb + g]);           \
            bf[j][1] = __float_as_uint(Bp[(kb+tig+4)*BSTR + nb + g]);         \
        }                                                                     \
        _Pragma("unroll")                                                     \
        for (int i = 0; i < 4; i++)                                           \
            _Pragma("unroll")                                                 \
            for (int j = 0; j < 8; j++)                                       \
                mma_tf32(acc[i][j], af[i], bf[j]);                            \
    }                                                                         \
} while (0)

#define G_MAINLOOP() do {                                                     \
    G_STAGE(0, 0);                                                            \
    _Pragma("unroll 1")                                                       \
    for (int i = 0; i < 32; i++) {                                            \
        int cur = i & 1;                                                      \
        if (i + 1 < 32) {                                                     \
            G_STAGE(1 - cur, (i+1)*32);                                       \
            asm volatile("cp.async.wait_group 1;");                           \
        } else {                                                              \
            asm volatile("cp.async.wait_group 0;");                           \
        }                                                                     \
        __syncthreads();                                                      \
        G_MMA(cur);                                                           \
        __syncthreads();                                                      \
    }                                                                         \
} while (0)

__global__ __launch_bounds__(128, 2)
void qkv_gemm_tf32(const float* __restrict__ xr,
                   const float* __restrict__ wq, const float* __restrict__ bq,
                   const float* __restrict__ wk, const float* __restrict__ bk,
                   const float* __restrict__ wv, const float* __restrict__ bv)
{
    extern __shared__ float gsm[];
    unsigned asA, asB;
    {
        unsigned base = (unsigned)__cvta_generic_to_shared(gsm);
        asA = base; asB = base + 2*ABUFB;
    }
    float* BsF = gsm + 2*128*ASTR;

    const float* W; const float* bias; float* out;
    int z = blockIdx.z;
    if (z == 0)      { W = wq; bias = bq; out = g_q; }
    else if (z == 1) { W = wk; bias = bk; out = g_k; }
    else             { W = wv; bias = bv; out = g_v; }

    const int KROW = DM, NROW = HK;
    int tid  = threadIdx.x;
    int w    = tid >> 5, lane = tid & 31;
    int g    = lane >> 2, tig = lane & 3;
    int wm   = w & 1, wn = w >> 1;
    int laneRow = (lane & 7) + ((lane >> 3) & 1) * 8;
    int laneCol = ((lane >> 4) & 1) * 4;
    int m0   = blockIdx.y * 128, n0 = blockIdx.x * 128;

    const float* aP = xr + (size_t)m0 * KROW;
    const float* bP = W + n0;

    float acc[4][8][4] = {};
    G_MAINLOOP();

    #pragma unroll
    for (int i = 0; i < 4; i++) {
        int r0m = m0 + wm*64 + i*16 + g;
        #pragma unroll
        for (int j = 0; j < 8; j++) {
            int n = n0 + wn*64 + j*8 + tig*2;
            int h = n >> 6, kd = n & 63;
            float bv0 = bias[n], bv1 = bias[n+1];
            int b0i = r0m >> 11, s0 = r0m & (S_LEN-1);
            size_t base0 = (((size_t)(b0i*NH + h) * S_LEN + s0) << 6) + kd;
            out[base0]     = acc[i][j][0] + bv0;
            out[base0 + 1] = acc[i][j][1] + bv1;
            int r1m = r0m + 8;
            int b1i = r1m >> 11, s1 = r1m & (S_LEN-1);
            size_t base1 = (((size_t)(b1i*NH + h) * S_LEN + s1) << 6) + kd;
            out[base1]     = acc[i][j][2] + bv0;
            out[base1 + 1] = acc[i][j][3] + bv1;
        }
    }
}

__global__ __launch_bounds__(128, 2)
void out_gemm_tf32(const float* __restrict__ wo,
                   const float* __restrict__ bo,
                   float* __restrict__ C)
{
    extern __shared__ float gsm[];
    unsigned asA, asB;
    {
        unsigned base = (unsigned)__cvta_generic_to_shared(gsm);
        asA = base; asB = base + 2*ABUFB;
    }
    float* BsF = gsm + 2*128*ASTR;

    const int KROW = HK, NROW = DM;
    int tid  = threadIdx.x;
    int w    = tid >> 5, lane = tid & 31;
    int g    = lane >> 2, tig = lane & 3;
    int wm   = w & 1, wn = w >> 1;
    int laneRow = (lane & 7) + ((lane >> 3) & 1) * 8;
    int laneCol = ((lane >> 4) & 1) * 4;
    int m0   = blockIdx.y * 128, n0 = blockIdx.x * 128;

    const float* aP = g_o + (size_t)m0 * KROW;
    const float* bP = wo + n0;

    float acc[4][8][4] = {};
    G_MAINLOOP();

    #pragma unroll
    for (int i = 0; i < 4; i++) {
        int r0m = m0 + wm*64 + i*16 + g;
        #pragma unroll
        for (int j = 0; j < 8; j++) {
            int n = n0 + wn*64 + j*8 + tig*2;
            float bv0 = bo[n], bv1 = bo[n+1];
            float2 o0 = make_float2(acc[i][j][0] + bv0, acc[i][j][1] + bv1);
            float2 o1 = make_float2(acc[i][j][2] + bv0, acc[i][j][3] + bv1);
            *(float2*)&C[(size_t)r0m * DM + n]       = o0;
            *(float2*)&C[(size_t)(r0m+8) * DM + n]   = o1;
        }
    }
}

// =====================================================================
// Flash attention on tf32 tensor cores (R4 known-good; epilogue rounds g_o).
// keytile 64, smem 64 KB -> 2 CTA/SM. 256 threads (8 warps x 16 q rows).
// =====================================================================
#define ATTN_SMEM (16384 * 4)   // 64 KB

__global__ __launch_bounds__(256, 2)
void attn_mma()
{
    extern __shared__ unsigned su[];
    unsigned* KB = su;            // 4096
    unsigned* VB = su + 4096;     // 4096
    unsigned* PA = su + 8192;     // 8192

    int tid  = threadIdx.x;
    int w    = tid >> 5, lane = tid & 31;
    int g    = lane >> 2, tig = lane & 3;
    int bh   = blockIdx.y;
    int b    = bh >> 4, h = bh & 15;
    int q0   = blockIdx.x * 128;

    const float* qp = g_q + (size_t)bh * S_LEN * HD;
    const float* kp = g_k + (size_t)bh * S_LEN * HD;
    const float* vp = g_v + (size_t)bh * S_LEN * HD;

    float* Qs = (float*)su;
    #pragma unroll
    for (int it = 0; it < 8; it++) {
        int linear = it*256 + tid;
        int j = linear >> 4, d0 = (linear & 15) * 4;
        *(float4*)&Qs[j*64 + d0] = *(const float4*)&qp[(size_t)(q0 + j)*HD + d0];
    }
    __syncthreads();
    unsigned qf[8][4];
    #pragma unroll
    for (int kt = 0; kt < 8; kt++) {
        qf[kt][0] = f2tf32(Qs[(16*w+g  )*64 + kt*8 + tig  ]);
        qf[kt][1] = f2tf32(Qs[(16*w+g+8)*64 + kt*8 + tig  ]);
        qf[kt][2] = f2tf32(Qs[(16*w+g  )*64 + kt*8 + tig+4]);
        qf[kt][3] = f2tf32(Qs[(16*w+g+8)*64 + kt*8 + tig+4]);
    }
    __syncthreads();

    float o_acc[8][4] = {};
    float m0 = -1e30f, m1 = -1e30f, l0 = 0.f, l1 = 0.f;

    for (int t0 = 0; t0 < S_LEN; t0 += 64) {
        #pragma unroll
        for (int it = 0; it < 4; it++) {
            int linear = it*256 + tid;
            int j = linear >> 4, d0 = (linear & 15) * 4;
            float4 kv = *(const float4*)&kp[(size_t)(t0+j)*HD + d0];
            {
                int kt = d0 >> 3, creg = (d0 >> 2) & 1;
                int nt = j >> 3, nin = j & 7;
                unsigned* dst = &KB[(((kt<<3)+nt)<<6) + (nin<<3) + creg];
                dst[0] = f2tf32(kv.x); dst[2] = f2tf32(kv.y);
                dst[4] = f2tf32(kv.z); dst[6] = f2tf32(kv.w);
            }
            float4 vv = *(const float4*)&vp[(size_t)(t0+j)*HD + d0];
            {
                int ktv = j >> 3, kin = j & 7;
                int ntv = d0 >> 3;
                unsigned* dv = &VB[(((ktv<<3)+ntv)<<6) + (((d0&7)*4 + (kin&3))<<1) + (kin>>2)];
                dv[0]  = f2tf32(vv.x); dv[8]  = f2tf32(vv.y);
                dv[16] = f2tf32(vv.z); dv[24] = f2tf32(vv.w);
            }
        }
        __syncthreads();

        float s[8][4];
        #pragma unroll
        for (int nt = 0; nt < 8; nt++) { s[nt][0]=0.f; s[nt][1]=0.f; s[nt][2]=0.f; s[nt][3]=0.f; }
        #pragma unroll
        for (int kt = 0; kt < 8; kt++) {
            #pragma unroll
            for (int nt = 0; nt < 8; nt++) {
                unsigned b2[2];
                *(uint2*)b2 = *(const uint2*)&KB[(((kt<<3)+nt)<<6) + (lane<<1)];
                mma_tf32(s[nt], qf[kt], b2);
            }
        }

        float mx0 = m0, mx1 = m1;
        #pragma unroll
        for (int nt = 0; nt < 8; nt++) {
            mx0 = fmaxf(mx0, fmaxf(s[nt][0], s[nt][1]) * 0.125f);
            mx1 = fmaxf(mx1, fmaxf(s[nt][2], s[nt][3]) * 0.125f);
        }
        mx0 = fmaxf(mx0, __shfl_xor_sync(0xffffffffu, mx0, 1));
        mx0 = fmaxf(mx0, __shfl_xor_sync(0xffffffffu, mx0, 2));
        mx1 = fmaxf(mx1, __shfl_xor_sync(0xffffffffu, mx1, 1));
        mx1 = fmaxf(mx1, __shfl_xor_sync(0xffffffffu, mx1, 2));

        float alpha0 = __expf(m0 - mx0);
        float alpha1 = __expf(m1 - mx1);
        m0 = mx0; m1 = mx1;

        float sum0 = 0.f, sum1 = 0.f;
        unsigned* paw = PA + w*1024;
        #pragma unroll
        for (int nt = 0; nt < 8; nt++) {
            float p00 = __expf(s[nt][0]*0.125f - mx0);
            float p01 = __expf(s[nt][1]*0.125f - mx0);
            float p10 = __expf(s[nt][2]*0.125f - mx1);
            float p11 = __expf(s[nt][3]*0.125f - mx1);
            sum0 += p00 + p01;
            sum1 += p10 + p11;
            int c0 = 2*tig;
            int regsel = (c0 < 4) ? 0 : 2;
            unsigned* base = &paw[((nt<<5) + 4*g + (c0&3)) * 4 + regsel];
            *(uint2*)base       = make_uint2(f2tf32(p00), f2tf32(p10));
            *(uint2*)(base + 4) = make_uint2(f2tf32(p01), f2tf32(p11));
        }
        sum0 += __shfl_xor_sync(0xffffffffu, sum0, 1);
        sum0 += __shfl_xor_sync(0xffffffffu, sum0, 2);
        sum1 += __shfl_xor_sync(0xffffffffu, sum1, 1);
        sum1 += __shfl_xor_sync(0xffffffffu, sum1, 2);
        l0 = l0*alpha0 + sum0;
        l1 = l1*alpha1 + sum1;

        #pragma unroll
        for (int nt = 0; nt < 8; nt++) {
            o_acc[nt][0] *= alpha0; o_acc[nt][1] *= alpha0;
            o_acc[nt][2] *= alpha1; o_acc[nt][3] *= alpha1;
        }
        __syncwarp();

        #pragma unroll
        for (int kt = 0; kt < 8; kt++) {
            unsigned pa[4];
            *(uint4*)pa = *(const uint4*)&paw[((kt<<5) + lane) * 4];
            #pragma unroll
            for (int nt = 0; nt < 8; nt++) {
                unsigned b2[2];
                *(uint2*)b2 = *(const uint2*)&VB[(((kt<<3)+nt)<<6) + (lane<<1)];
                mma_tf32(o_acc[nt], pa, b2);
            }
        }
        __syncthreads();
    }

    // epilogue: write tf32-rounded so out_gemm's raw staging keeps rna accuracy
    float inv0 = 1.0f / l0, inv1 = 1.0f / l1;
    int r0 = q0 + 16*w + g, r1 = r0 + 8;
    #pragma unroll
    for (int nt = 0; nt < 8; nt++) {
        int c = nt*8 + 2*tig;
        *(float2*)&g_o[(size_t)(b*S_LEN + r0)*HK + h*64 + c] =
            make_float2(f2tf32f(o_acc[nt][0]*inv0), f2tf32f(o_acc[nt][1]*inv0));
        *(float2*)&g_o[(size_t)(b*S_LEN + r1)*HK + h*64 + c] =
            make_float2(f2tf32f(o_acc[nt][2]*inv1), f2tf32f(o_acc[nt][3]*inv1));
    }
}

// =====================================================================
extern "C" void kernel_launch(void* const* d_in, const int* in_sizes, int n_in,
                              void* d_out, int out_size)
{
    (void)in_sizes; (void)n_in; (void)out_size;
    const float* x  = (const float*)d_in[0];
    const float* Wq = (const float*)d_in[1];
    const float* bq = (const float*)d_in[2];
    const float* Wk = (const float*)d_in[3];
    const float* bk = (const float*)d_in[4];
    const float* Wv = (const float*)d_in[5];
    const float* bv = (const float*)d_in[6];
    const float* Wo = (const float*)d_in[7];
    const float* bo = (const float*)d_in[8];
    float* out = (float*)d_out;

    // tf32 pre-round (keeps rna accuracy through cp.async raw staging)
    round_pre<<<(MROWS*DM/4 + 255)/256, 256>>>(x, g_xr, MROWS*DM/4);
    round_pre<<<(DM*HK/4 + 255)/256, 256>>>(Wq, g_wq, DM*HK/4);
    round_pre<<<(DM*HK/4 + 255)/256, 256>>>(Wk, g_wk, DM*HK/4);
    round_pre<<<(DM*HK/4 + 255)/256, 256>>>(Wv, g_wv, DM*HK/4);
    round_pre<<<(HK*DM/4 + 255)/256, 256>>>(Wo, g_wo, HK*DM/4);

    cudaFuncSetAttribute(qkv_gemm_tf32, cudaFuncAttributeMaxDynamicSharedMemorySize, GEMM_SMEM);
    cudaFuncSetAttribute(out_gemm_tf32, cudaFuncAttributeMaxDynamicSharedMemorySize, GEMM_SMEM);
    cudaFuncSetAttribute(attn_mma, cudaFuncAttributeMaxDynamicSharedMemorySize, ATTN_SMEM);

    qkv_gemm_tf32<<<dim3(HK/128, MROWS/128, 3), 128, GEMM_SMEM>>>(
        g_xr, g_wq, bq, g_wk, bk, g_wv, bv);

    attn_mma<<<dim3(S_LEN/128, B_SZ*NH), 256, ATTN_SMEM>>>();

    out_gemm_tf32<<<dim3(DM/128, MROWS/128), 128, GEMM_SMEM>>>(g_wo, bo, out);
}

// round 9
// speedup vs baseline: 1.3262x; 1.3262x over previous
#include <cuda_runtime.h>

#define S_LEN   2048
#define B_SZ    2
#define DM      1024
#define NH      16
#define HD      64
#define HK      1024            // NH*HD
#define MROWS   (B_SZ*S_LEN)    // 4096

// ---------------- scratch (static device arrays; no allocation) -------------
__device__ float g_q[B_SZ*NH*S_LEN*HD];
__device__ float g_k[B_SZ*NH*S_LEN*HD];
__device__ float g_v[B_SZ*NH*S_LEN*HD];
__device__ float g_o[MROWS*HK];           // tf32-rounded by attn epilogue
__device__ float g_xr[MROWS*DM];          // tf32-rounded inputs
__device__ float g_wq[DM*HK], g_wk[DM*HK], g_wv[DM*HK], g_wo[HK*DM];

// ---------------- helpers ----------------------------------------------------
__device__ __forceinline__ unsigned f2tf32(float f) {
    unsigned r;
    asm("cvt.rna.tf32.f32 %0, %1;" : "=r"(r) : "f"(f));
    return r;
}
__device__ __forceinline__ float f2tf32f(float f) {
    float r;
    asm("cvt.rna.tf32.f32 %0, %1;" : "=f"(r) : "f"(f));
    return r;
}

__device__ __forceinline__ void mma_tf32(float* c, const unsigned* a, const unsigned* b) {
    asm volatile(
        "mma.sync.aligned.m16n8k8.row.col.f32.tf32.tf32.f32 "
        "{%0,%1,%2,%3}, {%4,%5,%6,%7}, {%8,%9}, {%0,%1,%2,%3};\n"
        : "+f"(c[0]), "+f"(c[1]), "+f"(c[2]), "+f"(c[3])
        : "r"(a[0]), "r"(a[1]), "r"(a[2]), "r"(a[3]),
          "r"(b[0]), "r"(b[1]));
}

// ---------------- pre-round kernel (f32 -> tf32-rounded f32) -----------------
__global__ void round_pre(const float* __restrict__ src, float* __restrict__ dst, int n4)
{
    int i = blockIdx.x * 256 + threadIdx.x;
    if (i < n4) {
        float4 v = ((const float4*)src)[i];
        v.x = f2tf32f(v.x); v.y = f2tf32f(v.y);
        v.z = f2tf32f(v.z); v.w = f2tf32f(v.w);
        ((float4*)dst)[i] = v;
    }
}

// =====================================================================
// TF32 GEMM: CTA 128x128, 128 threads (4 warps 2x2), warp tile 64x64,
// K-chunk 16, double-buffered static smem (40 KB).
// A smem [m][20], B smem [n][20] (both K-major, pre-rounded tf32 floats).
// Fragments exclusively via ldmatrix.x4.
// =====================================================================
#define AKP 20                  // 16 k + 4 pad (words)
#define TBUF (128*AKP)          // 2560 words per buffer

// staging: 4 float4 per matrix per thread
#define G_LOAD(kk) do {                                                       \
    _Pragma("unroll")                                                         \
    for (int p = 0; p < 4; p++) {                                             \
        int la = p*128 + tid;                                                 \
        av[p]  = *(const float4*)&aP[(size_t)(la >> 2) * KROW + (kk) + (la & 3) * 4]; \
        bvv[p] = *(const float4*)&bP[(size_t)((kk) + (la >> 5)) * NROW + (la & 31) * 4]; \
    }                                                                         \
} while (0)

#define G_STAGE(buf) do {                                                     \
    float* Ab = smemArr + (buf)*TBUF;                                         \
    float* Bb = smemArr + 2*TBUF + (buf)*TBUF;                                \
    _Pragma("unroll")                                                         \
    for (int p = 0; p < 4; p++) {                                             \
        int la = p*128 + tid;                                                 \
        *(float4*)&Ab[(la >> 2)*AKP + (la & 3)*4] = av[p];                    \
        int kr = la >> 5, nc = (la & 31) * 4;                                 \
        Bb[(nc+0)*AKP + kr] = bvv[p].x;                                       \
        Bb[(nc+1)*AKP + kr] = bvv[p].y;                                       \
        Bb[(nc+2)*AKP + kr] = bvv[p].z;                                       \
        Bb[(nc+3)*AKP + kr] = bvv[p].w;                                       \
    }                                                                         \
} while (0)

#define LDSM4(r0,r1,r2,r3,addr)                                               \
    asm volatile("ldmatrix.sync.aligned.m8n8.x4.shared.b16 {%0,%1,%2,%3}, [%4];" \
        : "=r"(r0), "=r"(r1), "=r"(r2), "=r"(r3) : "r"(addr))

#define G_MMA(buf) do {                                                       \
    unsigned aB = smemBase + (buf)*(TBUF*4) + aFragOff;                       \
    unsigned bB = smemBase + (2*TBUF)*4 + (buf)*(TBUF*4) + bFragOff;          \
    _Pragma("unroll")                                                         \
    for (int kb = 0; kb < 16; kb += 8) {                                      \
        unsigned af[4][4], bf[8][2];                                          \
        _Pragma("unroll")                                                     \
        for (int i = 0; i < 4; i++)                                           \
            LDSM4(af[i][0], af[i][1], af[i][2], af[i][3],                     \
                  aB + (unsigned)((i*16*AKP + kb)*4));                        \
        _Pragma("unroll")                                                     \
        for (int jj = 0; jj < 4; jj++)                                        \
            LDSM4(bf[2*jj][0], bf[2*jj][1], bf[2*jj+1][0], bf[2*jj+1][1],     \
                  bB + (unsigned)((jj*16*AKP + kb)*4));                       \
        _Pragma("unroll")                                                     \
        for (int i = 0; i < 4; i++)                                           \
            _Pragma("unroll")                                                 \
            for (int j = 0; j < 8; j++)                                       \
                mma_tf32(acc[i][j], af[i], bf[j]);                            \
    }                                                                         \
} while (0)

#define G_MAINLOOP(KTOT) do {                                                 \
    G_LOAD(0);                                                                \
    G_STAGE(0);                                                               \
    __syncthreads();                                                          \
    _Pragma("unroll 1")                                                       \
    for (int k0 = 0; k0 < (KTOT); k0 += 16) {                                 \
        int cur = (k0 >> 4) & 1;                                              \
        bool more = (k0 + 16 < (KTOT));                                       \
        if (more) G_LOAD(k0 + 16);                                            \
        G_MMA(cur);                                                           \
        if (more) { if (cur) G_STAGE(0); else G_STAGE(1); }                   \
        __syncthreads();                                                      \
    }                                                                         \
} while (0)

// common per-thread setup for frag addressing
#define G_SETUP()                                                             \
    int tid  = threadIdx.x;                                                   \
    int w    = tid >> 5, lane = tid & 31;                                     \
    int g    = lane >> 2, tig = lane & 3;                                     \
    int wm   = w & 1, wn = w >> 1;                                            \
    int laneRowA = lane & 15;                                                 \
    int laneColA = (lane >> 4) * 4;                                           \
    int laneRowB = (lane & 7) + ((lane >> 4) & 1) * 8;                        \
    int laneColB = ((lane >> 3) & 1) * 4;                                     \
    unsigned smemBase = (unsigned)__cvta_generic_to_shared(smemArr);          \
    unsigned aFragOff = (unsigned)(((wm*64 + laneRowA)*AKP + laneColA)*4);    \
    unsigned bFragOff = (unsigned)(((wn*64 + laneRowB)*AKP + laneColB)*4)

__global__ __launch_bounds__(128, 2)
void qkv_gemm_tf32(const float* __restrict__ xr,
                   const float* __restrict__ wq, const float* __restrict__ bq,
                   const float* __restrict__ wk, const float* __restrict__ bk,
                   const float* __restrict__ wv, const float* __restrict__ bv)
{
    __shared__ float smemArr[4*TBUF];   // 40 KB

    const float* W; const float* bias; float* out;
    int z = blockIdx.z;
    if (z == 0)      { W = wq; bias = bq; out = g_q; }
    else if (z == 1) { W = wk; bias = bk; out = g_k; }
    else             { W = wv; bias = bv; out = g_v; }

    const int KROW = DM, NROW = HK;
    G_SETUP();
    int m0 = blockIdx.y * 128, n0 = blockIdx.x * 128;

    const float* aP = xr + (size_t)m0 * KROW;
    const float* bP = W + n0;

    float4 av[4], bvv[4];
    float acc[4][8][4] = {};
    G_MAINLOOP(DM);

    #pragma unroll
    for (int i = 0; i < 4; i++) {
        int r0m = m0 + wm*64 + i*16 + g;
        #pragma unroll
        for (int j = 0; j < 8; j++) {
            int n = n0 + wn*64 + j*8 + tig*2;
            int h = n >> 6, kd = n & 63;
            float bv0 = bias[n], bv1 = bias[n+1];
            int b0i = r0m >> 11, s0 = r0m & (S_LEN-1);
            size_t base0 = (((size_t)(b0i*NH + h) * S_LEN + s0) << 6) + kd;
            out[base0]     = acc[i][j][0] + bv0;
            out[base0 + 1] = acc[i][j][1] + bv1;
            int r1m = r0m + 8;
            int b1i = r1m >> 11, s1 = r1m & (S_LEN-1);
            size_t base1 = (((size_t)(b1i*NH + h) * S_LEN + s1) << 6) + kd;
            out[base1]     = acc[i][j][2] + bv0;
            out[base1 + 1] = acc[i][j][3] + bv1;
        }
    }
}

__global__ __launch_bounds__(128, 2)
void out_gemm_tf32(const float* __restrict__ wo,
                   const float* __restrict__ bo,
                   float* __restrict__ C)
{
    __shared__ float smemArr[4*TBUF];   // 40 KB

    const int KROW = HK, NROW = DM;
    G_SETUP();
    int m0 = blockIdx.y * 128, n0 = blockIdx.x * 128;

    const float* aP = g_o + (size_t)m0 * KROW;
    const float* bP = wo + n0;

    float4 av[4], bvv[4];
    float acc[4][8][4] = {};
    G_MAINLOOP(HK);

    #pragma unroll
    for (int i = 0; i < 4; i++) {
        int r0m = m0 + wm*64 + i*16 + g;
        #pragma unroll
        for (int j = 0; j < 8; j++) {
            int n = n0 + wn*64 + j*8 + tig*2;
            float bv0 = bo[n], bv1 = bo[n+1];
            float2 o0 = make_float2(acc[i][j][0] + bv0, acc[i][j][1] + bv1);
            float2 o1 = make_float2(acc[i][j][2] + bv0, acc[i][j][3] + bv1);
            *(float2*)&C[(size_t)r0m * DM + n]       = o0;
            *(float2*)&C[(size_t)(r0m+8) * DM + n]   = o1;
        }
    }
}

// =====================================================================
// Flash attention on tf32 tensor cores (R7 known-good; epilogue rounds g_o).
// keytile 64, smem 64 KB -> 2 CTA/SM. 256 threads (8 warps x 16 q rows).
// =====================================================================
#define ATTN_SMEM (16384 * 4)   // 64 KB

__global__ __launch_bounds__(256, 2)
void attn_mma()
{
    extern __shared__ unsigned su[];
    unsigned* KB = su;            // 4096
    unsigned* VB = su + 4096;     // 4096
    unsigned* PA = su + 8192;     // 8192

    int tid  = threadIdx.x;
    int w    = tid >> 5, lane = tid & 31;
    int g    = lane >> 2, tig = lane & 3;
    int bh   = blockIdx.y;
    int b    = bh >> 4, h = bh & 15;
    int q0   = blockIdx.x * 128;

    const float* qp = g_q + (size_t)bh * S_LEN * HD;
    const float* kp = g_k + (size_t)bh * S_LEN * HD;
    const float* vp = g_v + (size_t)bh * S_LEN * HD;

    float* Qs = (float*)su;
    #pragma unroll
    for (int it = 0; it < 8; it++) {
        int linear = it*256 + tid;
        int j = linear >> 4, d0 = (linear & 15) * 4;
        *(float4*)&Qs[j*64 + d0] = *(const float4*)&qp[(size_t)(q0 + j)*HD + d0];
    }
    __syncthreads();
    unsigned qf[8][4];
    #pragma unroll
    for (int kt = 0; kt < 8; kt++) {
        qf[kt][0] = f2tf32(Qs[(16*w+g  )*64 + kt*8 + tig  ]);
        qf[kt][1] = f2tf32(Qs[(16*w+g+8)*64 + kt*8 + tig  ]);
        qf[kt][2] = f2tf32(Qs[(16*w+g  )*64 + kt*8 + tig+4]);
        qf[kt][3] = f2tf32(Qs[(16*w+g+8)*64 + kt*8 + tig+4]);
    }
    __syncthreads();

    float o_acc[8][4] = {};
    float m0 = -1e30f, m1 = -1e30f, l0 = 0.f, l1 = 0.f;

    for (int t0 = 0; t0 < S_LEN; t0 += 64) {
        #pragma unroll
        for (int it = 0; it < 4; it++) {
            int linear = it*256 + tid;
            int j = linear >> 4, d0 = (linear & 15) * 4;
            float4 kv = *(const float4*)&kp[(size_t)(t0+j)*HD + d0];
            {
                int kt = d0 >> 3, creg = (d0 >> 2) & 1;
                int nt = j >> 3, nin = j & 7;
                unsigned* dst = &KB[(((kt<<3)+nt)<<6) + (nin<<3) + creg];
                dst[0] = f2tf32(kv.x); dst[2] = f2tf32(kv.y);
                dst[4] = f2tf32(kv.z); dst[6] = f2tf32(kv.w);
            }
            float4 vv = *(const float4*)&vp[(size_t)(t0+j)*HD + d0];
            {
                int ktv = j >> 3, kin = j & 7;
                int ntv = d0 >> 3;
                unsigned* dv = &VB[(((ktv<<3)+ntv)<<6) + (((d0&7)*4 + (kin&3))<<1) + (kin>>2)];
                dv[0]  = f2tf32(vv.x); dv[8]  = f2tf32(vv.y);
                dv[16] = f2tf32(vv.z); dv[24] = f2tf32(vv.w);
            }
        }
        __syncthreads();

        float s[8][4];
        #pragma unroll
        for (int nt = 0; nt < 8; nt++) { s[nt][0]=0.f; s[nt][1]=0.f; s[nt][2]=0.f; s[nt][3]=0.f; }
        #pragma unroll
        for (int kt = 0; kt < 8; kt++) {
            #pragma unroll
            for (int nt = 0; nt < 8; nt++) {
                unsigned b2[2];
                *(uint2*)b2 = *(const uint2*)&KB[(((kt<<3)+nt)<<6) + (lane<<1)];
                mma_tf32(s[nt], qf[kt], b2);
            }
        }

        float mx0 = m0, mx1 = m1;
        #pragma unroll
        for (int nt = 0; nt < 8; nt++) {
            mx0 = fmaxf(mx0, fmaxf(s[nt][0], s[nt][1]) * 0.125f);
            mx1 = fmaxf(mx1, fmaxf(s[nt][2], s[nt][3]) * 0.125f);
        }
        mx0 = fmaxf(mx0, __shfl_xor_sync(0xffffffffu, mx0, 1));
        mx0 = fmaxf(mx0, __shfl_xor_sync(0xffffffffu, mx0, 2));
        mx1 = fmaxf(mx1, __shfl_xor_sync(0xffffffffu, mx1, 1));
        mx1 = fmaxf(mx1, __shfl_xor_sync(0xffffffffu, mx1, 2));

        float alpha0 = __expf(m0 - mx0);
        float alpha1 = __expf(m1 - mx1);
        m0 = mx0; m1 = mx1;

        float sum0 = 0.f, sum1 = 0.f;
        unsigned* paw = PA + w*1024;
        #pragma unroll
        for (int nt = 0; nt < 8; nt++) {
            float p00 = __expf(s[nt][0]*0.125f - mx0);
            float p01 = __expf(s[nt][1]*0.125f - mx0);
            float p10 = __expf(s[nt][2]*0.125f - mx1);
            float p11 = __expf(s[nt][3]*0.125f - mx1);
            sum0 += p00 + p01;
            sum1 += p10 + p11;
            int c0 = 2*tig;
            int regsel = (c0 < 4) ? 0 : 2;
            unsigned* base = &paw[((nt<<5) + 4*g + (c0&3)) * 4 + regsel];
            *(uint2*)base       = make_uint2(f2tf32(p00), f2tf32(p10));
            *(uint2*)(base + 4) = make_uint2(f2tf32(p01), f2tf32(p11));
        }
        sum0 += __shfl_xor_sync(0xffffffffu, sum0, 1);
        sum0 += __shfl_xor_sync(0xffffffffu, sum0, 2);
        sum1 += __shfl_xor_sync(0xffffffffu, sum1, 1);
        sum1 += __shfl_xor_sync(0xffffffffu, sum1, 2);
        l0 = l0*alpha0 + sum0;
        l1 = l1*alpha1 + sum1;

        #pragma unroll
        for (int nt = 0; nt < 8; nt++) {
            o_acc[nt][0] *= alpha0; o_acc[nt][1] *= alpha0;
            o_acc[nt][2] *= alpha1; o_acc[nt][3] *= alpha1;
        }
        __syncwarp();

        #pragma unroll
        for (int kt = 0; kt < 8; kt++) {
            unsigned pa[4];
            *(uint4*)pa = *(const uint4*)&paw[((kt<<5) + lane) * 4];
            #pragma unroll
            for (int nt = 0; nt < 8; nt++) {
                unsigned b2[2];
                *(uint2*)b2 = *(const uint2*)&VB[(((kt<<3)+nt)<<6) + (lane<<1)];
                mma_tf32(o_acc[nt], pa, b2);
            }
        }
        __syncthreads();
    }

    // epilogue: tf32-rounded so out_gemm's raw staging keeps rna accuracy
    float inv0 = 1.0f / l0, inv1 = 1.0f / l1;
    int r0 = q0 + 16*w + g, r1 = r0 + 8;
    #pragma unroll
    for (int nt = 0; nt < 8; nt++) {
        int c = nt*8 + 2*tig;
        *(float2*)&g_o[(size_t)(b*S_LEN + r0)*HK + h*64 + c] =
            make_float2(f2tf32f(o_acc[nt][0]*inv0), f2tf32f(o_acc[nt][1]*inv0));
        *(float2*)&g_o[(size_t)(b*S_LEN + r1)*HK + h*64 + c] =
            make_float2(f2tf32f(o_acc[nt][2]*inv1), f2tf32f(o_acc[nt][3]*inv1));
    }
}

// =====================================================================
extern "C" void kernel_launch(void* const* d_in, const int* in_sizes, int n_in,
                              void* d_out, int out_size)
{
    (void)in_sizes; (void)n_in; (void)out_size;
    const float* x  = (const float*)d_in[0];
    const float* Wq = (const float*)d_in[1];
    const float* bq = (const float*)d_in[2];
    const float* Wk = (const float*)d_in[3];
    const float* bk = (const float*)d_in[4];
    const float* Wv = (const float*)d_in[5];
    const float* bv = (const float*)d_in[6];
    const float* Wo = (const float*)d_in[7];
    const float* bo = (const float*)d_in[8];
    float* out = (float*)d_out;

    // tf32 pre-round (keeps rna accuracy with raw f4 staging)
    round_pre<<<(MROWS*DM/4 + 255)/256, 256>>>(x, g_xr, MROWS*DM/4);
    round_pre<<<(DM*HK/4 + 255)/256, 256>>>(Wq, g_wq, DM*HK/4);
    round_pre<<<(DM*HK/4 + 255)/256, 256>>>(Wk, g_wk, DM*HK/4);
    round_pre<<<(DM*HK/4 + 255)/256, 256>>>(Wv, g_wv, DM*HK/4);
    round_pre<<<(HK*DM/4 + 255)/256, 256>>>(Wo, g_wo, HK*DM/4);

    cudaFuncSetAttribute(attn_mma, cudaFuncAttributeMaxDynamicSharedMemorySize, ATTN_SMEM);

    qkv_gemm_tf32<<<dim3(HK/128, MROWS/128, 3), 128>>>(
        g_xr, g_wq, bq, g_wk, bk, g_wv, bv);

    attn_mma<<<dim3(S_LEN/128, B_SZ*NH), 256, ATTN_SMEM>>>();

    out_gemm_tf32<<<dim3(DM/128, MROWS/128), 128>>>(g_wo, bo, out);
}

// round 10
// speedup vs baseline: 10.1248x; 7.6344x over previous
#include <cuda_runtime.h>

#define S_LEN   2048
#define B_SZ    2
#define DM      1024
#define NH      16
#define HD      64
#define HK      1024            // NH*HD
#define MROWS   (B_SZ*S_LEN)    // 4096

// ---------------- scratch (static device arrays; no allocation) -------------
__device__ float g_q[B_SZ*NH*S_LEN*HD];   // (b,h,s,k)
__device__ float g_k[B_SZ*NH*S_LEN*HD];
__device__ float g_v[B_SZ*NH*S_LEN*HD];
__device__ float g_o[MROWS*HK];           // (b,s,hk)

// ---------------- tf32 helpers ----------------------------------------------
__device__ __forceinline__ unsigned f2tf32(float f) {
    unsigned r;
    asm("cvt.rna.tf32.f32 %0, %1;" : "=r"(r) : "f"(f));
    return r;
}

__device__ __forceinline__ void mma_tf32(float* c, const unsigned* a, const unsigned* b) {
    asm volatile(
        "mma.sync.aligned.m16n8k8.row.col.f32.tf32.tf32.f32 "
        "{%0,%1,%2,%3}, {%4,%5,%6,%7}, {%8,%9}, {%0,%1,%2,%3};\n"
        : "+f"(c[0]), "+f"(c[1]), "+f"(c[2]), "+f"(c[3])
        : "r"(a[0]), "r"(a[1]), "r"(a[2]), "r"(a[3]),
          "r"(b[0]), "r"(b[1]));
}

// =====================================================================
// TF32 GEMM (exact R7 checkpoint): CTA 128x128x16, 128 threads (4 warps 2x2),
// warp tile 64x64, double-buffered smem, cvt-in-staging.
// =====================================================================
#define GS 132

#define GEMM_STAGE64(buf) do {                                                \
    _Pragma("unroll")                                                         \
    for (int p = 0; p < 4; p++) {                                             \
        int la = p*128 + tid;                                                 \
        int row = la >> 2, kc = (la & 3) * 4;                                 \
        As[buf][kc+0][row] = f2tf32(av[p].x);                                 \
        As[buf][kc+1][row] = f2tf32(av[p].y);                                 \
        As[buf][kc+2][row] = f2tf32(av[p].z);                                 \
        As[buf][kc+3][row] = f2tf32(av[p].w);                                 \
        int lb = p*128 + tid;                                                 \
        int kr = lb >> 5, nc = (lb & 31) * 4;                                 \
        Bs[buf][kr][nc+0] = f2tf32(bvv[p].x);                                 \
        Bs[buf][kr][nc+1] = f2tf32(bvv[p].y);                                 \
        Bs[buf][kr][nc+2] = f2tf32(bvv[p].z);                                 \
        Bs[buf][kr][nc+3] = f2tf32(bvv[p].w);                                 \
    }                                                                         \
} while (0)

#define GEMM_LOAD64(kbase) do {                                               \
    _Pragma("unroll")                                                         \
    for (int p = 0; p < 4; p++) {                                             \
        int la = p*128 + tid;                                                 \
        av[p]  = *(const float4*)&aP[(size_t)(la >> 2) * KROW + (kbase) + (la & 3) * 4]; \
        int lb = p*128 + tid;                                                 \
        bvv[p] = *(const float4*)&bP[(size_t)((kbase) + (lb >> 5)) * NROW + (lb & 31) * 4]; \
    }                                                                         \
} while (0)

#define GEMM_MMA64(buf) do {                                                  \
    _Pragma("unroll")                                                         \
    for (int ks = 0; ks < 2; ks++) {                                          \
        int kb = ks * 8;                                                      \
        unsigned af[4][4], bf[8][2];                                          \
        _Pragma("unroll")                                                     \
        for (int i = 0; i < 4; i++) {                                         \
            int mb = wm*64 + i*16;                                            \
            af[i][0] = As[buf][kb+tig  ][mb+g];                               \
            af[i][1] = As[buf][kb+tig  ][mb+g+8];                             \
            af[i][2] = As[buf][kb+tig+4][mb+g];                               \
            af[i][3] = As[buf][kb+tig+4][mb+g+8];                             \
        }                                                                     \
        _Pragma("unroll")                                                     \
        for (int j = 0; j < 8; j++) {                                         \
            int nb = wn*64 + j*8;                                             \
            bf[j][0] = Bs[buf][kb+tig  ][nb+g];                               \
            bf[j][1] = Bs[buf][kb+tig+4][nb+g];                               \
        }                                                                     \
        _Pragma("unroll")                                                     \
        for (int i = 0; i < 4; i++)                                           \
            _Pragma("unroll")                                                 \
            for (int j = 0; j < 8; j++)                                       \
                mma_tf32(acc[i][j], af[i], bf[j]);                            \
    }                                                                         \
} while (0)

__global__ __launch_bounds__(128, 2)
void qkv_gemm_tf32(const float* __restrict__ x,
                   const float* __restrict__ Wq, const float* __restrict__ bq,
                   const float* __restrict__ Wk, const float* __restrict__ bk,
                   const float* __restrict__ Wv, const float* __restrict__ bv)
{
    __shared__ unsigned As[2][16][GS];
    __shared__ unsigned Bs[2][16][GS];

    const float* W; const float* bias; float* out;
    int z = blockIdx.z;
    if (z == 0)      { W = Wq; bias = bq; out = g_q; }
    else if (z == 1) { W = Wk; bias = bk; out = g_k; }
    else             { W = Wv; bias = bv; out = g_v; }

    const int KROW = DM, NROW = HK;
    int tid  = threadIdx.x;
    int w    = tid >> 5, lane = tid & 31;
    int g    = lane >> 2, tig = lane & 3;
    int wm   = w & 1, wn = w >> 1;
    int m0   = blockIdx.y * 128, n0 = blockIdx.x * 128;

    const float* aP = x + (size_t)m0 * KROW;
    const float* bP = W + n0;

    float4 av[4], bvv[4];
    float acc[4][8][4] = {};

    GEMM_LOAD64(0);
    GEMM_STAGE64(0);
    __syncthreads();

    for (int k0 = 0; k0 < DM; k0 += 16) {
        int cur = (k0 >> 4) & 1;
        bool more = (k0 + 16 < DM);
        if (more) GEMM_LOAD64(k0 + 16);
        GEMM_MMA64(cur);
        if (more) {
            if (cur) GEMM_STAGE64(0); else GEMM_STAGE64(1);
        }
        __syncthreads();
    }

    #pragma unroll
    for (int i = 0; i < 4; i++) {
        int r0m = m0 + wm*64 + i*16 + g;
        #pragma unroll
        for (int j = 0; j < 8; j++) {
            int n = n0 + wn*64 + j*8 + tig*2;
            int h = n >> 6, kd = n & 63;
            float bv0 = bias[n], bv1 = bias[n+1];
            int b0i = r0m >> 11, s0 = r0m & (S_LEN-1);
            size_t base0 = (((size_t)(b0i*NH + h) * S_LEN + s0) << 6) + kd;
            out[base0]     = acc[i][j][0] + bv0;
            out[base0 + 1] = acc[i][j][1] + bv1;
            int r1m = r0m + 8;
            int b1i = r1m >> 11, s1 = r1m & (S_LEN-1);
            size_t base1 = (((size_t)(b1i*NH + h) * S_LEN + s1) << 6) + kd;
            out[base1]     = acc[i][j][2] + bv0;
            out[base1 + 1] = acc[i][j][3] + bv1;
        }
    }
}

__global__ __launch_bounds__(128, 2)
void out_gemm_tf32(const float* __restrict__ Wo,
                   const float* __restrict__ bo,
                   float* __restrict__ C)
{
    __shared__ unsigned As[2][16][GS];
    __shared__ unsigned Bs[2][16][GS];

    const int KROW = HK, NROW = DM;
    int tid  = threadIdx.x;
    int w    = tid >> 5, lane = tid & 31;
    int g    = lane >> 2, tig = lane & 3;
    int wm   = w & 1, wn = w >> 1;
    int m0   = blockIdx.y * 128, n0 = blockIdx.x * 128;

    const float* aP = g_o + (size_t)m0 * KROW;
    const float* bP = Wo + n0;

    float4 av[4], bvv[4];
    float acc[4][8][4] = {};

    GEMM_LOAD64(0);
    GEMM_STAGE64(0);
    __syncthreads();

    for (int k0 = 0; k0 < HK; k0 += 16) {
        int cur = (k0 >> 4) & 1;
        bool more = (k0 + 16 < HK);
        if (more) GEMM_LOAD64(k0 + 16);
        GEMM_MMA64(cur);
        if (more) {
            if (cur) GEMM_STAGE64(0); else GEMM_STAGE64(1);
        }
        __syncthreads();
    }

    #pragma unroll
    for (int i = 0; i < 4; i++) {
        int r0m = m0 + wm*64 + i*16 + g;
        #pragma unroll
        for (int j = 0; j < 8; j++) {
            int n = n0 + wn*64 + j*8 + tig*2;
            float bv0 = bo[n], bv1 = bo[n+1];
            float2 o0 = make_float2(acc[i][j][0] + bv0, acc[i][j][1] + bv1);
            float2 o1 = make_float2(acc[i][j][2] + bv0, acc[i][j][3] + bv1);
            *(float2*)&C[(size_t)r0m * DM + n]       = o0;
            *(float2*)&C[(size_t)(r0m+8) * DM + n]   = o1;
        }
    }
}

// =====================================================================
// Flash attention, tf32 MMA. Key tile 64, DOUBLE-BUFFERED K/V frags,
// ONE __syncthreads per iteration, exp2-domain softmax.
// Smem (words): KB0 0, KB1 4096, VB0 8192, VB1 12288, PA 16384 (8 KB/warp... 1024w/warp)
// total 24576 w = 96 KB -> 2 CTA/SM.
// =====================================================================
#define ATTN_SMEM (24576 * 4)
#define QSCALE 0.1803368801111204f   // 0.125 * log2(e)

// stage K/V tile (64 rows at t0) into buffer b
#define ATTN_STAGE(b, t0) do {                                                \
    _Pragma("unroll")                                                         \
    for (int f = 0; f < 4; f++) {                                             \
        int linear = f*256 + tid;                                             \
        int j = linear >> 4, d0 = (linear & 15) * 4;                          \
        float4 kv = *(const float4*)&kp[(size_t)((t0)+j)*HD + d0];            \
        {                                                                     \
            int kt = d0 >> 3, creg = (d0 >> 2) & 1;                           \
            int nt = j >> 3, nin = j & 7;                                     \
            unsigned* dst = &su[(b)*4096 + (((kt<<3)+nt)<<6) + (nin<<3) + creg]; \
            dst[0] = f2tf32(kv.x); dst[2] = f2tf32(kv.y);                     \
            dst[4] = f2tf32(kv.z); dst[6] = f2tf32(kv.w);                     \
        }                                                                     \
        float4 vv = *(const float4*)&vp[(size_t)((t0)+j)*HD + d0];            \
        {                                                                     \
            int ktv = j >> 3, kin = j & 7;                                    \
            int ntv = d0 >> 3;                                                \
            unsigned* dv = &su[8192 + (b)*4096 + (((ktv<<3)+ntv)<<6) +        \
                               (((d0&7)*4 + (kin&3))<<1) + (kin>>2)];         \
            dv[0]  = f2tf32(vv.x); dv[8]  = f2tf32(vv.y);                     \
            dv[16] = f2tf32(vv.z); dv[24] = f2tf32(vv.w);                     \
        }                                                                     \
    }                                                                         \
} while (0)

__global__ __launch_bounds__(256, 2)
void attn_mma()
{
    extern __shared__ unsigned su[];
    unsigned* PA = su + 16384;

    int tid  = threadIdx.x;
    int w    = tid >> 5, lane = tid & 31;
    int g    = lane >> 2, tig = lane & 3;
    int bh   = blockIdx.y;
    int b    = bh >> 4, h = bh & 15;
    int q0   = blockIdx.x * 128;

    const float* qp = g_q + (size_t)bh * S_LEN * HD;
    const float* kp = g_k + (size_t)bh * S_LEN * HD;
    const float* vp = g_v + (size_t)bh * S_LEN * HD;

    // ---- stage Q (scratch overlay on KB region), build prescaled qf ----
    float* Qs = (float*)su;    // 32 KB
    #pragma unroll
    for (int it = 0; it < 8; it++) {
        int linear = it*256 + tid;
        int j = linear >> 4, d0 = (linear & 15) * 4;
        *(float4*)&Qs[j*64 + d0] = *(const float4*)&qp[(size_t)(q0 + j)*HD + d0];
    }
    __syncthreads();
    unsigned qf[8][4];
    #pragma unroll
    for (int kt = 0; kt < 8; kt++) {
        qf[kt][0] = f2tf32(Qs[(16*w+g  )*64 + kt*8 + tig  ] * QSCALE);
        qf[kt][1] = f2tf32(Qs[(16*w+g+8)*64 + kt*8 + tig  ] * QSCALE);
        qf[kt][2] = f2tf32(Qs[(16*w+g  )*64 + kt*8 + tig+4] * QSCALE);
        qf[kt][3] = f2tf32(Qs[(16*w+g+8)*64 + kt*8 + tig+4] * QSCALE);
    }
    __syncthreads();

    // ---- prologue: stage tile 0 into buffer 0 ----
    ATTN_STAGE(0, 0);

    float o_acc[8][4] = {};
    float m0 = -1e30f, m1 = -1e30f, l0 = 0.f, l1 = 0.f;

    #pragma unroll 1
    for (int it = 0; it < S_LEN/64; it++) {
        int cur = it & 1;
        __syncthreads();   // buf[cur] staged; buf[1-cur] reads from it-1 done

        // ---- S = Q @ K^T (log2-domain logits) ----
        const unsigned* KBc = su + cur*4096;
        float s[8][4];
        #pragma unroll
        for (int nt = 0; nt < 8; nt++) { s[nt][0]=0.f; s[nt][1]=0.f; s[nt][2]=0.f; s[nt][3]=0.f; }
        #pragma unroll
        for (int kt = 0; kt < 8; kt++) {
            #pragma unroll
            for (int nt = 0; nt < 8; nt++) {
                unsigned b2[2];
                *(uint2*)b2 = *(const uint2*)&KBc[(((kt<<3)+nt)<<6) + (lane<<1)];
                mma_tf32(s[nt], qf[kt], b2);
            }
        }

        // ---- online softmax (exp2 domain, quad-local) ----
        float mx0 = m0, mx1 = m1;
        #pragma unroll
        for (int nt = 0; nt < 8; nt++) {
            mx0 = fmaxf(mx0, fmaxf(s[nt][0], s[nt][1]));
            mx1 = fmaxf(mx1, fmaxf(s[nt][2], s[nt][3]));
        }
        mx0 = fmaxf(mx0, __shfl_xor_sync(0xffffffffu, mx0, 1));
        mx0 = fmaxf(mx0, __shfl_xor_sync(0xffffffffu, mx0, 2));
        mx1 = fmaxf(mx1, __shfl_xor_sync(0xffffffffu, mx1, 1));
        mx1 = fmaxf(mx1, __shfl_xor_sync(0xffffffffu, mx1, 2));

        float alpha0 = exp2f(m0 - mx0);
        float alpha1 = exp2f(m1 - mx1);
        m0 = mx0; m1 = mx1;

        float sum0 = 0.f, sum1 = 0.f;
        unsigned* paw = PA + w*1024;
        #pragma unroll
        for (int nt = 0; nt < 8; nt++) {
            float p00 = exp2f(s[nt][0] - mx0);
            float p01 = exp2f(s[nt][1] - mx0);
            float p10 = exp2f(s[nt][2] - mx1);
            float p11 = exp2f(s[nt][3] - mx1);
            sum0 += p00 + p01;
            sum1 += p10 + p11;
            int c0 = 2*tig;
            int regsel = (c0 < 4) ? 0 : 2;
            unsigned* base = &paw[((nt<<5) + 4*g + (c0&3)) * 4 + regsel];
            *(uint2*)base       = make_uint2(f2tf32(p00), f2tf32(p10));
            *(uint2*)(base + 4) = make_uint2(f2tf32(p01), f2tf32(p11));
        }
        sum0 += __shfl_xor_sync(0xffffffffu, sum0, 1);
        sum0 += __shfl_xor_sync(0xffffffffu, sum0, 2);
        sum1 += __shfl_xor_sync(0xffffffffu, sum1, 1);
        sum1 += __shfl_xor_sync(0xffffffffu, sum1, 2);
        l0 = l0*alpha0 + sum0;
        l1 = l1*alpha1 + sum1;

        #pragma unroll
        for (int nt = 0; nt < 8; nt++) {
            o_acc[nt][0] *= alpha0; o_acc[nt][1] *= alpha0;
            o_acc[nt][2] *= alpha1; o_acc[nt][3] *= alpha1;
        }
        __syncwarp();

        // ---- O += P @ V (from buf[cur]) ----
        const unsigned* VBc = su + 8192 + cur*4096;
        #pragma unroll
        for (int kt = 0; kt < 8; kt++) {
            unsigned pa[4];
            *(uint4*)pa = *(const uint4*)&paw[((kt<<5) + lane) * 4];
            #pragma unroll
            for (int nt = 0; nt < 8; nt++) {
                unsigned b2[2];
                *(uint2*)b2 = *(const uint2*)&VBc[(((kt<<3)+nt)<<6) + (lane<<1)];
                mma_tf32(o_acc[nt], pa, b2);
            }
        }

        // ---- stage next tile into the other buffer (overlaps; sync at top) ----
        if (it + 1 < S_LEN/64) {
            ATTN_STAGE(1 - cur, (it + 1) * 64);
        }
    }

    // ---- epilogue ----
    float inv0 = 1.0f / l0, inv1 = 1.0f / l1;
    int r0 = q0 + 16*w + g, r1 = r0 + 8;
    #pragma unroll
    for (int nt = 0; nt < 8; nt++) {
        int c = nt*8 + 2*tig;
        *(float2*)&g_o[(size_t)(b*S_LEN + r0)*HK + h*64 + c] =
            make_float2(o_acc[nt][0]*inv0, o_acc[nt][1]*inv0);
        *(float2*)&g_o[(size_t)(b*S_LEN + r1)*HK + h*64 + c] =
            make_float2(o_acc[nt][2]*inv1, o_acc[nt][3]*inv1);
    }
}

// =====================================================================
extern "C" void kernel_launch(void* const* d_in, const int* in_sizes, int n_in,
                              void* d_out, int out_size)
{
    (void)in_sizes; (void)n_in; (void)out_size;
    const float* x  = (const float*)d_in[0];
    const float* Wq = (const float*)d_in[1];
    const float* bq = (const float*)d_in[2];
    const float* Wk = (const float*)d_in[3];
    const float* bk = (const float*)d_in[4];
    const float* Wv = (const float*)d_in[5];
    const float* bv = (const float*)d_in[6];
    const float* Wo = (const float*)d_in[7];
    const float* bo = (const float*)d_in[8];
    float* out = (float*)d_out;

    qkv_gemm_tf32<<<dim3(HK/128, MROWS/128, 3), 128>>>(x, Wq, bq, Wk, bk, Wv, bv);

    cudaFuncSetAttribute(attn_mma, cudaFuncAttributeMaxDynamicSharedMemorySize, ATTN_SMEM);
    attn_mma<<<dim3(S_LEN/128, B_SZ*NH), 256, ATTN_SMEM>>>();

    out_gemm_tf32<<<dim3(DM/128, MROWS/128), 128>>>(Wo, bo, out);
}

// round 11
// speedup vs baseline: 10.7217x; 1.0590x over previous
#include <cuda_runtime.h>

#define S_LEN   2048
#define B_SZ    2
#define DM      1024
#define NH      16
#define HD      64
#define HK      1024            // NH*HD
#define MROWS   (B_SZ*S_LEN)    // 4096

// ---------------- scratch (static device arrays; no allocation) -------------
__device__ float g_q[B_SZ*NH*S_LEN*HD];   // (b,h,s,k)
__device__ float g_k[B_SZ*NH*S_LEN*HD];
__device__ float g_v[B_SZ*NH*S_LEN*HD];
__device__ float g_o[MROWS*HK];           // (b,s,hk)

// ---------------- tf32 helpers ----------------------------------------------
__device__ __forceinline__ unsigned f2tf32(float f) {
    unsigned r;
    asm("cvt.rna.tf32.f32 %0, %1;" : "=r"(r) : "f"(f));
    return r;
}

__device__ __forceinline__ void mma_tf32(float* c, const unsigned* a, const unsigned* b) {
    asm volatile(
        "mma.sync.aligned.m16n8k8.row.col.f32.tf32.tf32.f32 "
        "{%0,%1,%2,%3}, {%4,%5,%6,%7}, {%8,%9}, {%0,%1,%2,%3};\n"
        : "+f"(c[0]), "+f"(c[1]), "+f"(c[2]), "+f"(c[3])
        : "r"(a[0]), "r"(a[1]), "r"(a[2]), "r"(a[3]),
          "r"(b[0]), "r"(b[1]));
}

// =====================================================================
// TF32 GEMM (exact R7 checkpoint): CTA 128x128x16, 128 threads (4 warps 2x2),
// warp tile 64x64, double-buffered smem, cvt-in-staging.
// =====================================================================
#define GS 132

#define GEMM_STAGE64(buf) do {                                                \
    _Pragma("unroll")                                                         \
    for (int p = 0; p < 4; p++) {                                             \
        int la = p*128 + tid;                                                 \
        int row = la >> 2, kc = (la & 3) * 4;                                 \
        As[buf][kc+0][row] = f2tf32(av[p].x);                                 \
        As[buf][kc+1][row] = f2tf32(av[p].y);                                 \
        As[buf][kc+2][row] = f2tf32(av[p].z);                                 \
        As[buf][kc+3][row] = f2tf32(av[p].w);                                 \
        int lb = p*128 + tid;                                                 \
        int kr = lb >> 5, nc = (lb & 31) * 4;                                 \
        Bs[buf][kr][nc+0] = f2tf32(bvv[p].x);                                 \
        Bs[buf][kr][nc+1] = f2tf32(bvv[p].y);                                 \
        Bs[buf][kr][nc+2] = f2tf32(bvv[p].z);                                 \
        Bs[buf][kr][nc+3] = f2tf32(bvv[p].w);                                 \
    }                                                                         \
} while (0)

#define GEMM_LOAD64(kbase) do {                                               \
    _Pragma("unroll")                                                         \
    for (int p = 0; p < 4; p++) {                                             \
        int la = p*128 + tid;                                                 \
        av[p]  = *(const float4*)&aP[(size_t)(la >> 2) * KROW + (kbase) + (la & 3) * 4]; \
        int lb = p*128 + tid;                                                 \
        bvv[p] = *(const float4*)&bP[(size_t)((kbase) + (lb >> 5)) * NROW + (lb & 31) * 4]; \
    }                                                                         \
} while (0)

#define GEMM_MMA64(buf) do {                                                  \
    _Pragma("unroll")                                                         \
    for (int ks = 0; ks < 2; ks++) {                                          \
        int kb = ks * 8;                                                      \
        unsigned af[4][4], bf[8][2];                                          \
        _Pragma("unroll")                                                     \
        for (int i = 0; i < 4; i++) {                                         \
            int mb = wm*64 + i*16;                                            \
            af[i][0] = As[buf][kb+tig  ][mb+g];                               \
            af[i][1] = As[buf][kb+tig  ][mb+g+8];                             \
            af[i][2] = As[buf][kb+tig+4][mb+g];                               \
            af[i][3] = As[buf][kb+tig+4][mb+g+8];                             \
        }                                                                     \
        _Pragma("unroll")                                                     \
        for (int j = 0; j < 8; j++) {                                         \
            int nb = wn*64 + j*8;                                             \
            bf[j][0] = Bs[buf][kb+tig  ][nb+g];                               \
            bf[j][1] = Bs[buf][kb+tig+4][nb+g];                               \
        }                                                                     \
        _Pragma("unroll")                                                     \
        for (int i = 0; i < 4; i++)                                           \
            _Pragma("unroll")                                                 \
            for (int j = 0; j < 8; j++)                                       \
                mma_tf32(acc[i][j], af[i], bf[j]);                            \
    }                                                                         \
} while (0)

__global__ __launch_bounds__(128, 2)
void qkv_gemm_tf32(const float* __restrict__ x,
                   const float* __restrict__ Wq, const float* __restrict__ bq,
                   const float* __restrict__ Wk, const float* __restrict__ bk,
                   const float* __restrict__ Wv, const float* __restrict__ bv)
{
    __shared__ unsigned As[2][16][GS];
    __shared__ unsigned Bs[2][16][GS];

    const float* W; const float* bias; float* out;
    int z = blockIdx.z;
    if (z == 0)      { W = Wq; bias = bq; out = g_q; }
    else if (z == 1) { W = Wk; bias = bk; out = g_k; }
    else             { W = Wv; bias = bv; out = g_v; }

    const int KROW = DM, NROW = HK;
    int tid  = threadIdx.x;
    int w    = tid >> 5, lane = tid & 31;
    int g    = lane >> 2, tig = lane & 3;
    int wm   = w & 1, wn = w >> 1;
    int m0   = blockIdx.y * 128, n0 = blockIdx.x * 128;

    const float* aP = x + (size_t)m0 * KROW;
    const float* bP = W + n0;

    float4 av[4], bvv[4];
    float acc[4][8][4] = {};

    GEMM_LOAD64(0);
    GEMM_STAGE64(0);
    __syncthreads();

    for (int k0 = 0; k0 < DM; k0 += 16) {
        int cur = (k0 >> 4) & 1;
        bool more = (k0 + 16 < DM);
        if (more) GEMM_LOAD64(k0 + 16);
        GEMM_MMA64(cur);
        if (more) {
            if (cur) GEMM_STAGE64(0); else GEMM_STAGE64(1);
        }
        __syncthreads();
    }

    #pragma unroll
    for (int i = 0; i < 4; i++) {
        int r0m = m0 + wm*64 + i*16 + g;
        #pragma unroll
        for (int j = 0; j < 8; j++) {
            int n = n0 + wn*64 + j*8 + tig*2;
            int h = n >> 6, kd = n & 63;
            float bv0 = bias[n], bv1 = bias[n+1];
            int b0i = r0m >> 11, s0 = r0m & (S_LEN-1);
            size_t base0 = (((size_t)(b0i*NH + h) * S_LEN + s0) << 6) + kd;
            out[base0]     = acc[i][j][0] + bv0;
            out[base0 + 1] = acc[i][j][1] + bv1;
            int r1m = r0m + 8;
            int b1i = r1m >> 11, s1 = r1m & (S_LEN-1);
            size_t base1 = (((size_t)(b1i*NH + h) * S_LEN + s1) << 6) + kd;
            out[base1]     = acc[i][j][2] + bv0;
            out[base1 + 1] = acc[i][j][3] + bv1;
        }
    }
}

__global__ __launch_bounds__(128, 2)
void out_gemm_tf32(const float* __restrict__ Wo,
                   const float* __restrict__ bo,
                   float* __restrict__ C)
{
    __shared__ unsigned As[2][16][GS];
    __shared__ unsigned Bs[2][16][GS];

    const int KROW = HK, NROW = DM;
    int tid  = threadIdx.x;
    int w    = tid >> 5, lane = tid & 31;
    int g    = lane >> 2, tig = lane & 3;
    int wm   = w & 1, wn = w >> 1;
    int m0   = blockIdx.y * 128, n0 = blockIdx.x * 128;

    const float* aP = g_o + (size_t)m0 * KROW;
    const float* bP = Wo + n0;

    float4 av[4], bvv[4];
    float acc[4][8][4] = {};

    GEMM_LOAD64(0);
    GEMM_STAGE64(0);
    __syncthreads();

    for (int k0 = 0; k0 < HK; k0 += 16) {
        int cur = (k0 >> 4) & 1;
        bool more = (k0 + 16 < HK);
        if (more) GEMM_LOAD64(k0 + 16);
        GEMM_MMA64(cur);
        if (more) {
            if (cur) GEMM_STAGE64(0); else GEMM_STAGE64(1);
        }
        __syncthreads();
    }

    #pragma unroll
    for (int i = 0; i < 4; i++) {
        int r0m = m0 + wm*64 + i*16 + g;
        #pragma unroll
        for (int j = 0; j < 8; j++) {
            int n = n0 + wn*64 + j*8 + tig*2;
            float bv0 = bo[n], bv1 = bo[n+1];
            float2 o0 = make_float2(acc[i][j][0] + bv0, acc[i][j][1] + bv1);
            float2 o1 = make_float2(acc[i][j][2] + bv0, acc[i][j][3] + bv1);
            *(float2*)&C[(size_t)r0m * DM + n]       = o0;
            *(float2*)&C[(size_t)(r0m+8) * DM + n]   = o1;
        }
    }
}

// =====================================================================
// Flash attention, tf32 MMA, M=32 per warp (2 m-tiles), 4 warps / 128 thr,
// q-tile 128, key tile 64, double-buffered K/V, one sync per iter,
// exp2-domain softmax. Each K/V B-fragment feeds 2 MMAs.
// Smem (words): KB0 0, KB1 4096, VB0 8192, VB1 12288, PA 16384 (2048 w/warp)
// total 24576 w = 96 KB -> 2 CTA/SM.
// =====================================================================
#define ATTN_SMEM (24576 * 4)
#define QSCALE 0.1803368801111204f   // 0.125 * log2(e)

#define ATTN_STAGE(b, t0) do {                                                \
    _Pragma("unroll")                                                         \
    for (int f = 0; f < 8; f++) {                                             \
        int linear = f*128 + tid;                                             \
        int j = linear >> 4, d0 = (linear & 15) * 4;                          \
        float4 kv = *(const float4*)&kp[(size_t)((t0)+j)*HD + d0];            \
        {                                                                     \
            int kt = d0 >> 3, creg = (d0 >> 2) & 1;                           \
            int nt = j >> 3, nin = j & 7;                                     \
            unsigned* dst = &su[(b)*4096 + (((kt<<3)+nt)<<6) + (nin<<3) + creg]; \
            dst[0] = f2tf32(kv.x); dst[2] = f2tf32(kv.y);                     \
            dst[4] = f2tf32(kv.z); dst[6] = f2tf32(kv.w);                     \
        }                                                                     \
        float4 vv = *(const float4*)&vp[(size_t)((t0)+j)*HD + d0];            \
        {                                                                     \
            int ktv = j >> 3, kin = j & 7;                                    \
            int ntv = d0 >> 3;                                                \
            unsigned* dv = &su[8192 + (b)*4096 + (((ktv<<3)+ntv)<<6) +        \
                               (((d0&7)*4 + (kin&3))<<1) + (kin>>2)];         \
            dv[0]  = f2tf32(vv.x); dv[8]  = f2tf32(vv.y);                     \
            dv[16] = f2tf32(vv.z); dv[24] = f2tf32(vv.w);                     \
        }                                                                     \
    }                                                                         \
} while (0)

__global__ __launch_bounds__(128, 2)
void attn_mma()
{
    extern __shared__ unsigned su[];
    unsigned* PA = su + 16384;

    int tid  = threadIdx.x;
    int w    = tid >> 5, lane = tid & 31;
    int g    = lane >> 2, tig = lane & 3;
    int bh   = blockIdx.y;
    int b    = bh >> 4, h = bh & 15;
    int q0   = blockIdx.x * 128;

    const float* qp = g_q + (size_t)bh * S_LEN * HD;
    const float* kp = g_k + (size_t)bh * S_LEN * HD;
    const float* vp = g_v + (size_t)bh * S_LEN * HD;

    // ---- stage Q (scratch overlay), build prescaled fragments (2 m-tiles) ----
    float* Qs = (float*)su;    // 128x64 f32 = 32 KB
    #pragma unroll
    for (int it = 0; it < 16; it++) {
        int linear = it*128 + tid;
        int j = linear >> 4, d0 = (linear & 15) * 4;
        *(float4*)&Qs[j*64 + d0] = *(const float4*)&qp[(size_t)(q0 + j)*HD + d0];
    }
    __syncthreads();
    unsigned qf[2][8][4];
    #pragma unroll
    for (int mi = 0; mi < 2; mi++) {
        int rbase = 32*w + 16*mi;
        #pragma unroll
        for (int kt = 0; kt < 8; kt++) {
            qf[mi][kt][0] = f2tf32(Qs[(rbase+g  )*64 + kt*8 + tig  ] * QSCALE);
            qf[mi][kt][1] = f2tf32(Qs[(rbase+g+8)*64 + kt*8 + tig  ] * QSCALE);
            qf[mi][kt][2] = f2tf32(Qs[(rbase+g  )*64 + kt*8 + tig+4] * QSCALE);
            qf[mi][kt][3] = f2tf32(Qs[(rbase+g+8)*64 + kt*8 + tig+4] * QSCALE);
        }
    }
    __syncthreads();

    ATTN_STAGE(0, 0);

    float o_acc[2][8][4] = {};
    float mrun[2][2], lrun[2][2];
    #pragma unroll
    for (int mi = 0; mi < 2; mi++) {
        mrun[mi][0] = -1e30f; mrun[mi][1] = -1e30f;
        lrun[mi][0] = 0.f;    lrun[mi][1] = 0.f;
    }

    #pragma unroll 1
    for (int it = 0; it < S_LEN/64; it++) {
        int cur = it & 1;
        __syncthreads();

        // ---- S = Q @ K^T: each K frag feeds both m-tiles ----
        const unsigned* KBc = su + cur*4096;
        float s[2][8][4] = {};
        #pragma unroll
        for (int kt = 0; kt < 8; kt++) {
            #pragma unroll
            for (int nt = 0; nt < 8; nt++) {
                unsigned b2[2];
                *(uint2*)b2 = *(const uint2*)&KBc[(((kt<<3)+nt)<<6) + (lane<<1)];
                mma_tf32(s[0][nt], qf[0][kt], b2);
                mma_tf32(s[1][nt], qf[1][kt], b2);
            }
        }

        // ---- online softmax per m-tile (exp2 domain, quad-local) ----
        unsigned* paw = PA + w*2048;
        #pragma unroll
        for (int mi = 0; mi < 2; mi++) {
            float mx0 = mrun[mi][0], mx1 = mrun[mi][1];
            #pragma unroll
            for (int nt = 0; nt < 8; nt++) {
                mx0 = fmaxf(mx0, fmaxf(s[mi][nt][0], s[mi][nt][1]));
                mx1 = fmaxf(mx1, fmaxf(s[mi][nt][2], s[mi][nt][3]));
            }
            mx0 = fmaxf(mx0, __shfl_xor_sync(0xffffffffu, mx0, 1));
            mx0 = fmaxf(mx0, __shfl_xor_sync(0xffffffffu, mx0, 2));
            mx1 = fmaxf(mx1, __shfl_xor_sync(0xffffffffu, mx1, 1));
            mx1 = fmaxf(mx1, __shfl_xor_sync(0xffffffffu, mx1, 2));

            float alpha0 = exp2f(mrun[mi][0] - mx0);
            float alpha1 = exp2f(mrun[mi][1] - mx1);
            mrun[mi][0] = mx0; mrun[mi][1] = mx1;

            float sum0 = 0.f, sum1 = 0.f;
            unsigned* pam = paw + mi*1024;
            #pragma unroll
            for (int nt = 0; nt < 8; nt++) {
                float p00 = exp2f(s[mi][nt][0] - mx0);
                float p01 = exp2f(s[mi][nt][1] - mx0);
                float p10 = exp2f(s[mi][nt][2] - mx1);
                float p11 = exp2f(s[mi][nt][3] - mx1);
                sum0 += p00 + p01;
                sum1 += p10 + p11;
                int c0 = 2*tig;
                int regsel = (c0 < 4) ? 0 : 2;
                unsigned* base = &pam[((nt<<5) + 4*g + (c0&3)) * 4 + regsel];
                *(uint2*)base       = make_uint2(f2tf32(p00), f2tf32(p10));
                *(uint2*)(base + 4) = make_uint2(f2tf32(p01), f2tf32(p11));
            }
            sum0 += __shfl_xor_sync(0xffffffffu, sum0, 1);
            sum0 += __shfl_xor_sync(0xffffffffu, sum0, 2);
            sum1 += __shfl_xor_sync(0xffffffffu, sum1, 1);
            sum1 += __shfl_xor_sync(0xffffffffu, sum1, 2);
            lrun[mi][0] = lrun[mi][0]*alpha0 + sum0;
            lrun[mi][1] = lrun[mi][1]*alpha1 + sum1;

            #pragma unroll
            for (int nt = 0; nt < 8; nt++) {
                o_acc[mi][nt][0] *= alpha0; o_acc[mi][nt][1] *= alpha0;
                o_acc[mi][nt][2] *= alpha1; o_acc[mi][nt][3] *= alpha1;
            }
        }
        __syncwarp();

        // ---- O += P @ V: each V frag feeds both m-tiles ----
        const unsigned* VBc = su + 8192 + cur*4096;
        #pragma unroll
        for (int kt = 0; kt < 8; kt++) {
            unsigned pa0[4], pa1[4];
            *(uint4*)pa0 = *(const uint4*)&paw[((kt<<5) + lane) * 4];
            *(uint4*)pa1 = *(const uint4*)&paw[1024 + ((kt<<5) + lane) * 4];
            #pragma unroll
            for (int nt = 0; nt < 8; nt++) {
                unsigned b2[2];
                *(uint2*)b2 = *(const uint2*)&VBc[(((kt<<3)+nt)<<6) + (lane<<1)];
                mma_tf32(o_acc[0][nt], pa0, b2);
                mma_tf32(o_acc[1][nt], pa1, b2);
            }
        }

        if (it + 1 < S_LEN/64) {
            ATTN_STAGE(1 - cur, (it + 1) * 64);
        }
    }

    // ---- epilogue ----
    #pragma unroll
    for (int mi = 0; mi < 2; mi++) {
        float inv0 = 1.0f / lrun[mi][0], inv1 = 1.0f / lrun[mi][1];
        int r0 = q0 + 32*w + 16*mi + g, r1 = r0 + 8;
        #pragma unroll
        for (int nt = 0; nt < 8; nt++) {
            int c = nt*8 + 2*tig;
            *(float2*)&g_o[(size_t)(b*S_LEN + r0)*HK + h*64 + c] =
                make_float2(o_acc[mi][nt][0]*inv0, o_acc[mi][nt][1]*inv0);
            *(float2*)&g_o[(size_t)(b*S_LEN + r1)*HK + h*64 + c] =
                make_float2(o_acc[mi][nt][2]*inv1, o_acc[mi][nt][3]*inv1);
        }
    }
}

// =====================================================================
extern "C" void kernel_launch(void* const* d_in, const int* in_sizes, int n_in,
                              void* d_out, int out_size)
{
    (void)in_sizes; (void)n_in; (void)out_size;
    const float* x  = (const float*)d_in[0];
    const float* Wq = (const float*)d_in[1];
    const float* bq = (const float*)d_in[2];
    const float* Wk = (const float*)d_in[3];
    const float* bk = (const float*)d_in[4];
    const float* Wv = (const float*)d_in[5];
    const float* bv = (const float*)d_in[6];
    const float* Wo = (const float*)d_in[7];
    const float* bo = (const float*)d_in[8];
    float* out = (float*)d_out;

    qkv_gemm_tf32<<<dim3(HK/128, MROWS/128, 3), 128>>>(x, Wq, bq, Wk, bk, Wv, bv);

    cudaFuncSetAttribute(attn_mma, cudaFuncAttributeMaxDynamicSharedMemorySize, ATTN_SMEM);
    attn_mma<<<dim3(S_LEN/128, B_SZ*NH), 128, ATTN_SMEM>>>();

    out_gemm_tf32<<<dim3(DM/128, MROWS/128), 128>>>(Wo, bo, out);
}

// round 12
// speedup vs baseline: 12.1542x; 1.1336x over previous
#include <cuda_runtime.h>
#include <cuda_fp16.h>

#define S_LEN   2048
#define B_SZ    2
#define DM      1024
#define NH      16
#define HD      64
#define HK      1024            // NH*HD
#define MROWS   (B_SZ*S_LEN)    // 4096

// ---------------- scratch (static device arrays; no allocation) -------------
__device__ float g_q[B_SZ*NH*S_LEN*HD];   // (b,h,s,k)
__device__ float g_k[B_SZ*NH*S_LEN*HD];
__device__ float g_v[B_SZ*NH*S_LEN*HD];
__device__ float g_o[MROWS*HK];           // (b,s,hk)

// ---------------- helpers ----------------------------------------------------
__device__ __forceinline__ unsigned f2tf32(float f) {
    unsigned r;
    asm("cvt.rna.tf32.f32 %0, %1;" : "=r"(r) : "f"(f));
    return r;
}

__device__ __forceinline__ unsigned h2pack(float a, float b) {
    __half2 t = __floats2half2_rn(a, b);
    return *(unsigned*)&t;
}

__device__ __forceinline__ void mma_tf32(float* c, const unsigned* a, const unsigned* b) {
    asm volatile(
        "mma.sync.aligned.m16n8k8.row.col.f32.tf32.tf32.f32 "
        "{%0,%1,%2,%3}, {%4,%5,%6,%7}, {%8,%9}, {%0,%1,%2,%3};\n"
        : "+f"(c[0]), "+f"(c[1]), "+f"(c[2]), "+f"(c[3])
        : "r"(a[0]), "r"(a[1]), "r"(a[2]), "r"(a[3]),
          "r"(b[0]), "r"(b[1]));
}

__device__ __forceinline__ void mma_f16(float* c, const unsigned* a, const unsigned* b) {
    asm volatile(
        "mma.sync.aligned.m16n8k16.row.col.f32.f16.f16.f32 "
        "{%0,%1,%2,%3}, {%4,%5,%6,%7}, {%8,%9}, {%0,%1,%2,%3};\n"
        : "+f"(c[0]), "+f"(c[1]), "+f"(c[2]), "+f"(c[3])
        : "r"(a[0]), "r"(a[1]), "r"(a[2]), "r"(a[3]),
          "r"(b[0]), "r"(b[1]));
}

// =====================================================================
// FP16 GEMM: CTA 128x128, 128 threads (4 warps 2x2), warp tile 64x64,
// K-chunk 16 (one m16n8k16 k-step = 32 MMAs/warp), double-buffered.
// Smem: As[k2][m], Bs[k2][n] as packed half2 words (k2 = k-pair).
// =====================================================================
#define GS 132   // half2-word row stride

#define GEMM_STAGE16(buf) do {                                                \
    _Pragma("unroll")                                                         \
    for (int p = 0; p < 4; p++) {                                             \
        int la = p*128 + tid;                                                 \
        int row = la >> 2, kc = (la & 3) * 4;                                 \
        As[buf][(kc>>1)  ][row] = h2pack(av[p].x, av[p].y);                   \
        As[buf][(kc>>1)+1][row] = h2pack(av[p].z, av[p].w);                   \
    }                                                                         \
    _Pragma("unroll")                                                         \
    for (int p = 0; p < 2; p++) {                                             \
        int lb = p*128 + tid;                                                 \
        int kr2 = lb >> 5, nc = (lb & 31) * 4;                                \
        Bs[buf][kr2][nc+0] = h2pack(bv0[p].x, bv1[p].x);                      \
        Bs[buf][kr2][nc+1] = h2pack(bv0[p].y, bv1[p].y);                      \
        Bs[buf][kr2][nc+2] = h2pack(bv0[p].z, bv1[p].z);                      \
        Bs[buf][kr2][nc+3] = h2pack(bv0[p].w, bv1[p].w);                      \
    }                                                                         \
} while (0)

#define GEMM_LOAD16(kbase) do {                                               \
    _Pragma("unroll")                                                         \
    for (int p = 0; p < 4; p++) {                                             \
        int la = p*128 + tid;                                                 \
        av[p] = *(const float4*)&aP[(size_t)(la >> 2) * KROW + (kbase) + (la & 3) * 4]; \
    }                                                                         \
    _Pragma("unroll")                                                         \
    for (int p = 0; p < 2; p++) {                                             \
        int lb = p*128 + tid;                                                 \
        int kr2 = lb >> 5, nc = (lb & 31) * 4;                                \
        bv0[p] = *(const float4*)&bP[(size_t)((kbase) + 2*kr2    ) * NROW + nc]; \
        bv1[p] = *(const float4*)&bP[(size_t)((kbase) + 2*kr2 + 1) * NROW + nc]; \
    }                                                                         \
} while (0)

#define GEMM_MMA16(buf) do {                                                  \
    unsigned af[4][4], bf[8][2];                                              \
    _Pragma("unroll")                                                         \
    for (int i = 0; i < 4; i++) {                                             \
        int mb = wm*64 + i*16;                                                \
        af[i][0] = As[buf][tig  ][mb+g];                                      \
        af[i][1] = As[buf][tig  ][mb+g+8];                                    \
        af[i][2] = As[buf][tig+4][mb+g];                                      \
        af[i][3] = As[buf][tig+4][mb+g+8];                                    \
    }                                                                         \
    _Pragma("unroll")                                                         \
    for (int j = 0; j < 8; j++) {                                             \
        int nb = wn*64 + j*8;                                                 \
        bf[j][0] = Bs[buf][tig  ][nb+g];                                      \
        bf[j][1] = Bs[buf][tig+4][nb+g];                                      \
    }                                                                         \
    _Pragma("unroll")                                                         \
    for (int i = 0; i < 4; i++)                                               \
        _Pragma("unroll")                                                     \
        for (int j = 0; j < 8; j++)                                           \
            mma_f16(acc[i][j], af[i], bf[j]);                                 \
} while (0)

__global__ __launch_bounds__(128, 2)
void qkv_gemm_f16(const float* __restrict__ x,
                  const float* __restrict__ Wq, const float* __restrict__ bq,
                  const float* __restrict__ Wk, const float* __restrict__ bk,
                  const float* __restrict__ Wv, const float* __restrict__ bv)
{
    __shared__ unsigned As[2][8][GS];
    __shared__ unsigned Bs[2][8][GS];

    const float* W; const float* bias; float* out;
    int z = blockIdx.z;
    if (z == 0)      { W = Wq; bias = bq; out = g_q; }
    else if (z == 1) { W = Wk; bias = bk; out = g_k; }
    else             { W = Wv; bias = bv; out = g_v; }

    const int KROW = DM, NROW = HK;
    int tid  = threadIdx.x;
    int w    = tid >> 5, lane = tid & 31;
    int g    = lane >> 2, tig = lane & 3;
    int wm   = w & 1, wn = w >> 1;
    int m0   = blockIdx.y * 128, n0 = blockIdx.x * 128;

    const float* aP = x + (size_t)m0 * KROW;
    const float* bP = W + n0;

    float4 av[4], bv0[2], bv1[2];
    float acc[4][8][4] = {};

    GEMM_LOAD16(0);
    GEMM_STAGE16(0);
    __syncthreads();

    for (int k0 = 0; k0 < DM; k0 += 16) {
        int cur = (k0 >> 4) & 1;
        bool more = (k0 + 16 < DM);
        if (more) GEMM_LOAD16(k0 + 16);
        GEMM_MMA16(cur);
        if (more) {
            if (cur) GEMM_STAGE16(0); else GEMM_STAGE16(1);
        }
        __syncthreads();
    }

    #pragma unroll
    for (int i = 0; i < 4; i++) {
        int r0m = m0 + wm*64 + i*16 + g;
        #pragma unroll
        for (int j = 0; j < 8; j++) {
            int n = n0 + wn*64 + j*8 + tig*2;
            int h = n >> 6, kd = n & 63;
            float bvv0 = bias[n], bvv1 = bias[n+1];
            int b0i = r0m >> 11, s0 = r0m & (S_LEN-1);
            size_t base0 = (((size_t)(b0i*NH + h) * S_LEN + s0) << 6) + kd;
            out[base0]     = acc[i][j][0] + bvv0;
            out[base0 + 1] = acc[i][j][1] + bvv1;
            int r1m = r0m + 8;
            int b1i = r1m >> 11, s1 = r1m & (S_LEN-1);
            size_t base1 = (((size_t)(b1i*NH + h) * S_LEN + s1) << 6) + kd;
            out[base1]     = acc[i][j][2] + bvv0;
            out[base1 + 1] = acc[i][j][3] + bvv1;
        }
    }
}

__global__ __launch_bounds__(128, 2)
void out_gemm_f16(const float* __restrict__ Wo,
                  const float* __restrict__ bo,
                  float* __restrict__ C)
{
    __shared__ unsigned As[2][8][GS];
    __shared__ unsigned Bs[2][8][GS];

    const int KROW = HK, NROW = DM;
    int tid  = threadIdx.x;
    int w    = tid >> 5, lane = tid & 31;
    int g    = lane >> 2, tig = lane & 3;
    int wm   = w & 1, wn = w >> 1;
    int m0   = blockIdx.y * 128, n0 = blockIdx.x * 128;

    const float* aP = g_o + (size_t)m0 * KROW;
    const float* bP = Wo + n0;

    float4 av[4], bv0[2], bv1[2];
    float acc[4][8][4] = {};

    GEMM_LOAD16(0);
    GEMM_STAGE16(0);
    __syncthreads();

    for (int k0 = 0; k0 < HK; k0 += 16) {
        int cur = (k0 >> 4) & 1;
        bool more = (k0 + 16 < HK);
        if (more) GEMM_LOAD16(k0 + 16);
        GEMM_MMA16(cur);
        if (more) {
            if (cur) GEMM_STAGE16(0); else GEMM_STAGE16(1);
        }
        __syncthreads();
    }

    #pragma unroll
    for (int i = 0; i < 4; i++) {
        int r0m = m0 + wm*64 + i*16 + g;
        #pragma unroll
        for (int j = 0; j < 8; j++) {
            int n = n0 + wn*64 + j*8 + tig*2;
            float bvv0 = bo[n], bvv1 = bo[n+1];
            float2 o0 = make_float2(acc[i][j][0] + bvv0, acc[i][j][1] + bvv1);
            float2 o1 = make_float2(acc[i][j][2] + bvv0, acc[i][j][3] + bvv1);
            *(float2*)&C[(size_t)r0m * DM + n]       = o0;
            *(float2*)&C[(size_t)(r0m+8) * DM + n]   = o1;
        }
    }
}

// =====================================================================
// Flash attention, tf32 MMA (exact R11 state): M=32/warp, 4 warps,
// double-buffered K/V, one sync/iter, exp2 softmax.
// =====================================================================
#define ATTN_SMEM (24576 * 4)
#define QSCALE 0.1803368801111204f   // 0.125 * log2(e)

#define ATTN_STAGE(b, t0) do {                                                \
    _Pragma("unroll")                                                         \
    for (int f = 0; f < 8; f++) {                                             \
        int linear = f*128 + tid;                                             \
        int j = linear >> 4, d0 = (linear & 15) * 4;                          \
        float4 kv = *(const float4*)&kp[(size_t)((t0)+j)*HD + d0];            \
        {                                                                     \
            int kt = d0 >> 3, creg = (d0 >> 2) & 1;                           \
            int nt = j >> 3, nin = j & 7;                                     \
            unsigned* dst = &su[(b)*4096 + (((kt<<3)+nt)<<6) + (nin<<3) + creg]; \
            dst[0] = f2tf32(kv.x); dst[2] = f2tf32(kv.y);                     \
            dst[4] = f2tf32(kv.z); dst[6] = f2tf32(kv.w);                     \
        }                                                                     \
        float4 vv = *(const float4*)&vp[(size_t)((t0)+j)*HD + d0];            \
        {                                                                     \
            int ktv = j >> 3, kin = j & 7;                                    \
            int ntv = d0 >> 3;                                                \
            unsigned* dv = &su[8192 + (b)*4096 + (((ktv<<3)+ntv)<<6) +        \
                               (((d0&7)*4 + (kin&3))<<1) + (kin>>2)];         \
            dv[0]  = f2tf32(vv.x); dv[8]  = f2tf32(vv.y);                     \
            dv[16] = f2tf32(vv.z); dv[24] = f2tf32(vv.w);                     \
        }                                                                     \
    }                                                                         \
} while (0)

__global__ __launch_bounds__(128, 2)
void attn_mma()
{
    extern __shared__ unsigned su[];
    unsigned* PA = su + 16384;

    int tid  = threadIdx.x;
    int w    = tid >> 5, lane = tid & 31;
    int g    = lane >> 2, tig = lane & 3;
    int bh   = blockIdx.y;
    int b    = bh >> 4, h = bh & 15;
    int q0   = blockIdx.x * 128;

    const float* qp = g_q + (size_t)bh * S_LEN * HD;
    const float* kp = g_k + (size_t)bh * S_LEN * HD;
    const float* vp = g_v + (size_t)bh * S_LEN * HD;

    float* Qs = (float*)su;
    #pragma unroll
    for (int it = 0; it < 16; it++) {
        int linear = it*128 + tid;
        int j = linear >> 4, d0 = (linear & 15) * 4;
        *(float4*)&Qs[j*64 + d0] = *(const float4*)&qp[(size_t)(q0 + j)*HD + d0];
    }
    __syncthreads();
    unsigned qf[2][8][4];
    #pragma unroll
    for (int mi = 0; mi < 2; mi++) {
        int rbase = 32*w + 16*mi;
        #pragma unroll
        for (int kt = 0; kt < 8; kt++) {
            qf[mi][kt][0] = f2tf32(Qs[(rbase+g  )*64 + kt*8 + tig  ] * QSCALE);
            qf[mi][kt][1] = f2tf32(Qs[(rbase+g+8)*64 + kt*8 + tig  ] * QSCALE);
            qf[mi][kt][2] = f2tf32(Qs[(rbase+g  )*64 + kt*8 + tig+4] * QSCALE);
            qf[mi][kt][3] = f2tf32(Qs[(rbase+g+8)*64 + kt*8 + tig+4] * QSCALE);
        }
    }
    __syncthreads();

    ATTN_STAGE(0, 0);

    float o_acc[2][8][4] = {};
    float mrun[2][2], lrun[2][2];
    #pragma unroll
    for (int mi = 0; mi < 2; mi++) {
        mrun[mi][0] = -1e30f; mrun[mi][1] = -1e30f;
        lrun[mi][0] = 0.f;    lrun[mi][1] = 0.f;
    }

    #pragma unroll 1
    for (int it = 0; it < S_LEN/64; it++) {
        int cur = it & 1;
        __syncthreads();

        const unsigned* KBc = su + cur*4096;
        float s[2][8][4] = {};
        #pragma unroll
        for (int kt = 0; kt < 8; kt++) {
            #pragma unroll
            for (int nt = 0; nt < 8; nt++) {
                unsigned b2[2];
                *(uint2*)b2 = *(const uint2*)&KBc[(((kt<<3)+nt)<<6) + (lane<<1)];
                mma_tf32(s[0][nt], qf[0][kt], b2);
                mma_tf32(s[1][nt], qf[1][kt], b2);
            }
        }

        unsigned* paw = PA + w*2048;
        #pragma unroll
        for (int mi = 0; mi < 2; mi++) {
            float mx0 = mrun[mi][0], mx1 = mrun[mi][1];
            #pragma unroll
            for (int nt = 0; nt < 8; nt++) {
                mx0 = fmaxf(mx0, fmaxf(s[mi][nt][0], s[mi][nt][1]));
                mx1 = fmaxf(mx1, fmaxf(s[mi][nt][2], s[mi][nt][3]));
            }
            mx0 = fmaxf(mx0, __shfl_xor_sync(0xffffffffu, mx0, 1));
            mx0 = fmaxf(mx0, __shfl_xor_sync(0xffffffffu, mx0, 2));
            mx1 = fmaxf(mx1, __shfl_xor_sync(0xffffffffu, mx1, 1));
            mx1 = fmaxf(mx1, __shfl_xor_sync(0xffffffffu, mx1, 2));

            float alpha0 = exp2f(mrun[mi][0] - mx0);
            float alpha1 = exp2f(mrun[mi][1] - mx1);
            mrun[mi][0] = mx0; mrun[mi][1] = mx1;

            float sum0 = 0.f, sum1 = 0.f;
            unsigned* pam = paw + mi*1024;
            #pragma unroll
            for (int nt = 0; nt < 8; nt++) {
                float p00 = exp2f(s[mi][nt][0] - mx0);
                float p01 = exp2f(s[mi][nt][1] - mx0);
                float p10 = exp2f(s[mi][nt][2] - mx1);
                float p11 = exp2f(s[mi][nt][3] - mx1);
                sum0 += p00 + p01;
                sum1 += p10 + p11;
                int c0 = 2*tig;
                int regsel = (c0 < 4) ? 0 : 2;
                unsigned* base = &pam[((nt<<5) + 4*g + (c0&3)) * 4 + regsel];
                *(uint2*)base       = make_uint2(f2tf32(p00), f2tf32(p10));
                *(uint2*)(base + 4) = make_uint2(f2tf32(p01), f2tf32(p11));
            }
            sum0 += __shfl_xor_sync(0xffffffffu, sum0, 1);
            sum0 += __shfl_xor_sync(0xffffffffu, sum0, 2);
            sum1 += __shfl_xor_sync(0xffffffffu, sum1, 1);
            sum1 += __shfl_xor_sync(0xffffffffu, sum1, 2);
            lrun[mi][0] = lrun[mi][0]*alpha0 + sum0;
            lrun[mi][1] = lrun[mi][1]*alpha1 + sum1;

            #pragma unroll
            for (int nt = 0; nt < 8; nt++) {
                o_acc[mi][nt][0] *= alpha0; o_acc[mi][nt][1] *= alpha0;
                o_acc[mi][nt][2] *= alpha1; o_acc[mi][nt][3] *= alpha1;
            }
        }
        __syncwarp();

        const unsigned* VBc = su + 8192 + cur*4096;
        #pragma unroll
        for (int kt = 0; kt < 8; kt++) {
            unsigned pa0[4], pa1[4];
            *(uint4*)pa0 = *(const uint4*)&paw[((kt<<5) + lane) * 4];
            *(uint4*)pa1 = *(const uint4*)&paw[1024 + ((kt<<5) + lane) * 4];
            #pragma unroll
            for (int nt = 0; nt < 8; nt++) {
                unsigned b2[2];
                *(uint2*)b2 = *(const uint2*)&VBc[(((kt<<3)+nt)<<6) + (lane<<1)];
                mma_tf32(o_acc[0][nt], pa0, b2);
                mma_tf32(o_acc[1][nt], pa1, b2);
            }
        }

        if (it + 1 < S_LEN/64) {
            ATTN_STAGE(1 - cur, (it + 1) * 64);
        }
    }

    #pragma unroll
    for (int mi = 0; mi < 2; mi++) {
        float inv0 = 1.0f / lrun[mi][0], inv1 = 1.0f / lrun[mi][1];
        int r0 = q0 + 32*w + 16*mi + g, r1 = r0 + 8;
        #pragma unroll
        for (int nt = 0; nt < 8; nt++) {
            int c = nt*8 + 2*tig;
            *(float2*)&g_o[(size_t)(b*S_LEN + r0)*HK + h*64 + c] =
                make_float2(o_acc[mi][nt][0]*inv0, o_acc[mi][nt][1]*inv0);
            *(float2*)&g_o[(size_t)(b*S_LEN + r1)*HK + h*64 + c] =
                make_float2(o_acc[mi][nt][2]*inv1, o_acc[mi][nt][3]*inv1);
        }
    }
}

// =====================================================================
extern "C" void kernel_launch(void* const* d_in, const int* in_sizes, int n_in,
                              void* d_out, int out_size)
{
    (void)in_sizes; (void)n_in; (void)out_size;
    const float* x  = (const float*)d_in[0];
    const float* Wq = (const float*)d_in[1];
    const float* bq = (const float*)d_in[2];
    const float* Wk = (const float*)d_in[3];
    const float* bk = (const float*)d_in[4];
    const float* Wv = (const float*)d_in[5];
    const float* bv = (const float*)d_in[6];
    const float* Wo = (const float*)d_in[7];
    const float* bo = (const float*)d_in[8];
    float* out = (float*)d_out;

    qkv_gemm_f16<<<dim3(HK/128, MROWS/128, 3), 128>>>(x, Wq, bq, Wk, bk, Wv, bv);

    cudaFuncSetAttribute(attn_mma, cudaFuncAttributeMaxDynamicSharedMemorySize, ATTN_SMEM);
    attn_mma<<<dim3(S_LEN/128, B_SZ*NH), 128, ATTN_SMEM>>>();

    out_gemm_f16<<<dim3(DM/128, MROWS/128), 128>>>(Wo, bo, out);
}

// round 14
// speedup vs baseline: 15.5633x; 1.2805x over previous
#include <cuda_runtime.h>
#include <cuda_fp16.h>

#define S_LEN   2048
#define B_SZ    2
#define DM      1024
#define NH      16
#define HD      64
#define HK      1024            // NH*HD
#define MROWS   (B_SZ*S_LEN)    // 4096

// ---------------- scratch (static device arrays; no allocation) -------------
__device__ float g_q[B_SZ*NH*S_LEN*HD];   // (b,h,s,k)
__device__ float g_k[B_SZ*NH*S_LEN*HD];
__device__ float g_v[B_SZ*NH*S_LEN*HD];
__device__ float g_o[MROWS*HK];           // (b,s,hk)

// ---------------- helpers ----------------------------------------------------
__device__ __forceinline__ unsigned h2pack(float a, float b) {
    __half2 t = __floats2half2_rn(a, b);
    return *(unsigned*)&t;
}

__device__ __forceinline__ void mma_f16(float* c, const unsigned* a, const unsigned* b) {
    asm volatile(
        "mma.sync.aligned.m16n8k16.row.col.f32.f16.f16.f32 "
        "{%0,%1,%2,%3}, {%4,%5,%6,%7}, {%8,%9}, {%0,%1,%2,%3};\n"
        : "+f"(c[0]), "+f"(c[1]), "+f"(c[2]), "+f"(c[3])
        : "r"(a[0]), "r"(a[1]), "r"(a[2]), "r"(a[3]),
          "r"(b[0]), "r"(b[1]));
}

// =====================================================================
// FP16 GEMM (R12 checkpoint): CTA 128x128, 128 threads, warp tile 64x64,
// K-chunk 16, double-buffered.
// =====================================================================
#define GS 132

#define GEMM_STAGE16(buf) do {                                                \
    _Pragma("unroll")                                                         \
    for (int p = 0; p < 4; p++) {                                             \
        int la = p*128 + tid;                                                 \
        int row = la >> 2, kc = (la & 3) * 4;                                 \
        As[buf][(kc>>1)  ][row] = h2pack(av[p].x, av[p].y);                   \
        As[buf][(kc>>1)+1][row] = h2pack(av[p].z, av[p].w);                   \
    }                                                                         \
    _Pragma("unroll")                                                         \
    for (int p = 0; p < 2; p++) {                                             \
        int lb = p*128 + tid;                                                 \
        int kr2 = lb >> 5, nc = (lb & 31) * 4;                                \
        Bs[buf][kr2][nc+0] = h2pack(bv0[p].x, bv1[p].x);                      \
        Bs[buf][kr2][nc+1] = h2pack(bv0[p].y, bv1[p].y);                      \
        Bs[buf][kr2][nc+2] = h2pack(bv0[p].z, bv1[p].z);                      \
        Bs[buf][kr2][nc+3] = h2pack(bv0[p].w, bv1[p].w);                      \
    }                                                                         \
} while (0)

#define GEMM_LOAD16(kbase) do {                                               \
    _Pragma("unroll")                                                         \
    for (int p = 0; p < 4; p++) {                                             \
        int la = p*128 + tid;                                                 \
        av[p] = *(const float4*)&aP[(size_t)(la >> 2) * KROW + (kbase) + (la & 3) * 4]; \
    }                                                                         \
    _Pragma("unroll")                                                         \
    for (int p = 0; p < 2; p++) {                                             \
        int lb = p*128 + tid;                                                 \
        int kr2 = lb >> 5, nc = (lb & 31) * 4;                                \
        bv0[p] = *(const float4*)&bP[(size_t)((kbase) + 2*kr2    ) * NROW + nc]; \
        bv1[p] = *(const float4*)&bP[(size_t)((kbase) + 2*kr2 + 1) * NROW + nc]; \
    }                                                                         \
} while (0)

#define GEMM_MMA16(buf) do {                                                  \
    unsigned af[4][4], bf[8][2];                                              \
    _Pragma("unroll")                                                         \
    for (int i = 0; i < 4; i++) {                                             \
        int mb = wm*64 + i*16;                                                \
        af[i][0] = As[buf][tig  ][mb+g];                                      \
        af[i][1] = As[buf][tig  ][mb+g+8];                                    \
        af[i][2] = As[buf][tig+4][mb+g];                                      \
        af[i][3] = As[buf][tig+4][mb+g+8];                                    \
    }                                                                         \
    _Pragma("unroll")                                                         \
    for (int j = 0; j < 8; j++) {                                             \
        int nb = wn*64 + j*8;                                                 \
        bf[j][0] = Bs[buf][tig  ][nb+g];                                      \
        bf[j][1] = Bs[buf][tig+4][nb+g];                                      \
    }                                                                         \
    _Pragma("unroll")                                                         \
    for (int i = 0; i < 4; i++)                                               \
        _Pragma("unroll")                                                     \
        for (int j = 0; j < 8; j++)                                           \
            mma_f16(acc[i][j], af[i], bf[j]);                                 \
} while (0)

__global__ __launch_bounds__(128, 2)
void qkv_gemm_f16(const float* __restrict__ x,
                  const float* __restrict__ Wq, const float* __restrict__ bq,
                  const float* __restrict__ Wk, const float* __restrict__ bk,
                  const float* __restrict__ Wv, const float* __restrict__ bv)
{
    __shared__ unsigned As[2][8][GS];
    __shared__ unsigned Bs[2][8][GS];

    const float* W; const float* bias; float* out;
    int z = blockIdx.z;
    if (z == 0)      { W = Wq; bias = bq; out = g_q; }
    else if (z == 1) { W = Wk; bias = bk; out = g_k; }
    else             { W = Wv; bias = bv; out = g_v; }

    const int KROW = DM, NROW = HK;
    int tid  = threadIdx.x;
    int w    = tid >> 5, lane = tid & 31;
    int g    = lane >> 2, tig = lane & 3;
    int wm   = w & 1, wn = w >> 1;
    int m0   = blockIdx.y * 128, n0 = blockIdx.x * 128;

    const float* aP = x + (size_t)m0 * KROW;
    const float* bP = W + n0;

    float4 av[4], bv0[2], bv1[2];
    float acc[4][8][4] = {};

    GEMM_LOAD16(0);
    GEMM_STAGE16(0);
    __syncthreads();

    for (int k0 = 0; k0 < DM; k0 += 16) {
        int cur = (k0 >> 4) & 1;
        bool more = (k0 + 16 < DM);
        if (more) GEMM_LOAD16(k0 + 16);
        GEMM_MMA16(cur);
        if (more) {
            if (cur) GEMM_STAGE16(0); else GEMM_STAGE16(1);
        }
        __syncthreads();
    }

    #pragma unroll
    for (int i = 0; i < 4; i++) {
        int r0m = m0 + wm*64 + i*16 + g;
        #pragma unroll
        for (int j = 0; j < 8; j++) {
            int n = n0 + wn*64 + j*8 + tig*2;
            int h = n >> 6, kd = n & 63;
            float bvv0 = bias[n], bvv1 = bias[n+1];
            int b0i = r0m >> 11, s0 = r0m & (S_LEN-1);
            size_t base0 = (((size_t)(b0i*NH + h) * S_LEN + s0) << 6) + kd;
            out[base0]     = acc[i][j][0] + bvv0;
            out[base0 + 1] = acc[i][j][1] + bvv1;
            int r1m = r0m + 8;
            int b1i = r1m >> 11, s1 = r1m & (S_LEN-1);
            size_t base1 = (((size_t)(b1i*NH + h) * S_LEN + s1) << 6) + kd;
            out[base1]     = acc[i][j][2] + bvv0;
            out[base1 + 1] = acc[i][j][3] + bvv1;
        }
    }
}

__global__ __launch_bounds__(128, 2)
void out_gemm_f16(const float* __restrict__ Wo,
                  const float* __restrict__ bo,
                  float* __restrict__ C)
{
    __shared__ unsigned As[2][8][GS];
    __shared__ unsigned Bs[2][8][GS];

    const int KROW = HK, NROW = DM;
    int tid  = threadIdx.x;
    int w    = tid >> 5, lane = tid & 31;
    int g    = lane >> 2, tig = lane & 3;
    int wm   = w & 1, wn = w >> 1;
    int m0   = blockIdx.y * 128, n0 = blockIdx.x * 128;

    const float* aP = g_o + (size_t)m0 * KROW;
    const float* bP = Wo + n0;

    float4 av[4], bv0[2], bv1[2];
    float acc[4][8][4] = {};

    GEMM_LOAD16(0);
    GEMM_STAGE16(0);
    __syncthreads();

    for (int k0 = 0; k0 < HK; k0 += 16) {
        int cur = (k0 >> 4) & 1;
        bool more = (k0 + 16 < HK);
        if (more) GEMM_LOAD16(k0 + 16);
        GEMM_MMA16(cur);
        if (more) {
            if (cur) GEMM_STAGE16(0); else GEMM_STAGE16(1);
        }
        __syncthreads();
    }

    #pragma unroll
    for (int i = 0; i < 4; i++) {
        int r0m = m0 + wm*64 + i*16 + g;
        #pragma unroll
        for (int j = 0; j < 8; j++) {
            int n = n0 + wn*64 + j*8 + tig*2;
            float bvv0 = bo[n], bvv1 = bo[n+1];
            float2 o0 = make_float2(acc[i][j][0] + bvv0, acc[i][j][1] + bvv1);
            float2 o1 = make_float2(acc[i][j][2] + bvv0, acc[i][j][3] + bvv1);
            *(float2*)&C[(size_t)r0m * DM + n]       = o0;
            *(float2*)&C[(size_t)(r0m+8) * DM + n]   = o1;
        }
    }
}

// =====================================================================
// Flash attention, FP16 m16n8k16 MMA. M=32/warp (2 m-tiles), 4 warps,
// q-tile 128, key tile 64, double-buffered K/V, one sync/iter, exp2 softmax.
// Fragment smem layouts (u32 words):
//   KB[b][kt(4)][nt(8)][lane(32)][2]   : 2048 w/buf   (K B-frags, k=dim)
//   VB[b][kt(4)][nt(8)][lane(32)][2]   : 2048 w/buf   (V B-frags, k=key)
//   PA[warp(4)][mi(2)][nt(8)][row(16)][tig(4)] : 4096 w (P A-frags)
// Word map: KB0 0, KB1 2048, VB0 4096, VB1 6144, PA 8192.  Total 48 KB.
// =====================================================================
#define ATTN_SMEM (12288 * 4)
#define QSCALE 0.1803368801111204f   // 0.125 * log2(e)

#define ATTN_STAGE(bb, t0) do {                                               \
    _Pragma("unroll")                                                         \
    for (int f = 0; f < 8; f++) {                                             \
        int linear = f*128 + tid;                                             \
        int j = linear >> 4, d0 = (linear & 15) * 4;                          \
        float4 kv = *(const float4*)&kp[(size_t)((t0)+j)*HD + d0];            \
        {                                                                     \
            int kt = d0 >> 4, r = (d0 >> 3) & 1;                              \
            int nt = j >> 3;                                                  \
            int laneK = ((j & 7) << 2) + ((d0 & 7) >> 1);                     \
            unsigned* dst = &su[(bb)*2048 + ((((kt<<3)+nt)<<5) + laneK)*2 + r]; \
            dst[0] = h2pack(kv.x, kv.y);                                      \
            dst[2] = h2pack(kv.z, kv.w);                                      \
        }                                                                     \
        float4 vv = *(const float4*)&vp[(size_t)((t0)+j)*HD + d0];            \
        {                                                                     \
            int ktv = j >> 4, rv = (j >> 3) & 1;                              \
            int pairv = (j & 7) >> 1, ev = j & 1;                             \
            int ntv = d0 >> 3;                                                \
            __half* hb = (__half*)(su + 4096 + (bb)*2048);                    \
            int base = (((((ktv<<3)+ntv)<<5) + ((d0&7)<<2) + pairv)*2 + rv)*2 + ev; \
            hb[base     ] = __float2half(vv.x);                               \
            hb[base + 16] = __float2half(vv.y);                               \
            hb[base + 32] = __float2half(vv.z);                               \
            hb[base + 48] = __float2half(vv.w);                               \
        }                                                                     \
    }                                                                         \
} while (0)

__global__ __launch_bounds__(128, 2)
void attn_mma()
{
    extern __shared__ unsigned su[];
    unsigned* PA = su + 8192;

    int tid  = threadIdx.x;
    int w    = tid >> 5, lane = tid & 31;
    int g    = lane >> 2, tig = lane & 3;
    int bh   = blockIdx.y;
    int b    = bh >> 4, h = bh & 15;
    int q0   = blockIdx.x * 128;

    const float* qp = g_q + (size_t)bh * S_LEN * HD;
    const float* kp = g_k + (size_t)bh * S_LEN * HD;
    const float* vp = g_v + (size_t)bh * S_LEN * HD;

    // ---- stage Q (scratch overlay on KB/VB), build prescaled fp16 A-frags ----
    float* Qs = (float*)su;    // 128x64 f32 = 32 KB
    #pragma unroll
    for (int it = 0; it < 16; it++) {
        int linear = it*128 + tid;
        int j = linear >> 4, d0 = (linear & 15) * 4;
        *(float4*)&Qs[j*64 + d0] = *(const float4*)&qp[(size_t)(q0 + j)*HD + d0];
    }
    __syncthreads();
    unsigned qf[2][4][4];   // [mi][kt][reg]
    #pragma unroll
    for (int mi = 0; mi < 2; mi++) {
        int rbase = 32*w + 16*mi;
        #pragma unroll
        for (int kt = 0; kt < 4; kt++) {
            const float* r0p = &Qs[(rbase+g  )*64 + kt*16];
            const float* r1p = &Qs[(rbase+g+8)*64 + kt*16];
            qf[mi][kt][0] = h2pack(r0p[2*tig  ]*QSCALE, r0p[2*tig+1]*QSCALE);
            qf[mi][kt][1] = h2pack(r1p[2*tig  ]*QSCALE, r1p[2*tig+1]*QSCALE);
            qf[mi][kt][2] = h2pack(r0p[8+2*tig]*QSCALE, r0p[8+2*tig+1]*QSCALE);
            qf[mi][kt][3] = h2pack(r1p[8+2*tig]*QSCALE, r1p[8+2*tig+1]*QSCALE);
        }
    }
    __syncthreads();

    ATTN_STAGE(0, 0);

    float o_acc[2][8][4] = {};
    float mrun[2][2], lrun[2][2];
    #pragma unroll
    for (int mi = 0; mi < 2; mi++) {
        mrun[mi][0] = -1e30f; mrun[mi][1] = -1e30f;
        lrun[mi][0] = 0.f;    lrun[mi][1] = 0.f;
    }

    #pragma unroll 1
    for (int it = 0; it < S_LEN/64; it++) {
        int cur = it & 1;
        __syncthreads();

        // ---- S = Q @ K^T ----
        const unsigned* KBc = su + cur*2048;
        float s[2][8][4] = {};
        #pragma unroll
        for (int kt = 0; kt < 4; kt++) {
            #pragma unroll
            for (int nt = 0; nt < 8; nt++) {
                unsigned b2[2];
                *(uint2*)b2 = *(const uint2*)&KBc[((((kt<<3)+nt)<<5) + lane)*2];
                mma_f16(s[0][nt], qf[0][kt], b2);
                mma_f16(s[1][nt], qf[1][kt], b2);
            }
        }

        // ---- online softmax (exp2 domain, quad-local), pack P to fp16 ----
        unsigned* paw = PA + w*1024;
        #pragma unroll
        for (int mi = 0; mi < 2; mi++) {
            float mx0 = mrun[mi][0], mx1 = mrun[mi][1];
            #pragma unroll
            for (int nt = 0; nt < 8; nt++) {
                mx0 = fmaxf(mx0, fmaxf(s[mi][nt][0], s[mi][nt][1]));
                mx1 = fmaxf(mx1, fmaxf(s[mi][nt][2], s[mi][nt][3]));
            }
            mx0 = fmaxf(mx0, __shfl_xor_sync(0xffffffffu, mx0, 1));
            mx0 = fmaxf(mx0, __shfl_xor_sync(0xffffffffu, mx0, 2));
            mx1 = fmaxf(mx1, __shfl_xor_sync(0xffffffffu, mx1, 1));
            mx1 = fmaxf(mx1, __shfl_xor_sync(0xffffffffu, mx1, 2));

            float alpha0 = exp2f(mrun[mi][0] - mx0);
            float alpha1 = exp2f(mrun[mi][1] - mx1);
            mrun[mi][0] = mx0; mrun[mi][1] = mx1;

            float sum0 = 0.f, sum1 = 0.f;
            unsigned* pam = paw + mi*512;
            #pragma unroll
            for (int nt = 0; nt < 8; nt++) {
                float p00 = exp2f(s[mi][nt][0] - mx0);
                float p01 = exp2f(s[mi][nt][1] - mx0);
                float p10 = exp2f(s[mi][nt][2] - mx1);
                float p11 = exp2f(s[mi][nt][3] - mx1);
                sum0 += p00 + p01;
                sum1 += p10 + p11;
                pam[((nt<<4) + g    )*4 + tig] = h2pack(p00, p01);
                pam[((nt<<4) + g + 8)*4 + tig] = h2pack(p10, p11);
            }
            sum0 += __shfl_xor_sync(0xffffffffu, sum0, 1);
            sum0 += __shfl_xor_sync(0xffffffffu, sum0, 2);
            sum1 += __shfl_xor_sync(0xffffffffu, sum1, 1);
            sum1 += __shfl_xor_sync(0xffffffffu, sum1, 2);
            lrun[mi][0] = lrun[mi][0]*alpha0 + sum0;
            lrun[mi][1] = lrun[mi][1]*alpha1 + sum1;

            #pragma unroll
            for (int nt = 0; nt < 8; nt++) {
                o_acc[mi][nt][0] *= alpha0; o_acc[mi][nt][1] *= alpha0;
                o_acc[mi][nt][2] *= alpha1; o_acc[mi][nt][3] *= alpha1;
            }
        }
        __syncwarp();

        // ---- O += P @ V ----
        const unsigned* VBc = su + 4096 + cur*2048;
        #pragma unroll
        for (int kt = 0; kt < 4; kt++) {
            unsigned pa0[4], pa1[4];
            pa0[0] = paw[(((2*kt  )<<4) + g    )*4 + tig];
            pa0[1] = paw[(((2*kt  )<<4) + g + 8)*4 + tig];
            pa0[2] = paw[(((2*kt+1)<<4) + g    )*4 + tig];
            pa0[3] = paw[(((2*kt+1)<<4) + g + 8)*4 + tig];
            pa1[0] = paw[512 + (((2*kt  )<<4) + g    )*4 + tig];
            pa1[1] = paw[512 + (((2*kt  )<<4) + g + 8)*4 + tig];
            pa1[2] = paw[512 + (((2*kt+1)<<4) + g    )*4 + tig];
            pa1[3] = paw[512 + (((2*kt+1)<<4) + g + 8)*4 + tig];
            #pragma unroll
            for (int nt = 0; nt < 8; nt++) {
                unsigned b2[2];
                *(uint2*)b2 = *(const uint2*)&VBc[((((kt<<3)+nt)<<5) + lane)*2];
                mma_f16(o_acc[0][nt], pa0, b2);
                mma_f16(o_acc[1][nt], pa1, b2);
            }
        }

        if (it + 1 < S_LEN/64) {
            ATTN_STAGE(1 - cur, (it + 1) * 64);
        }
    }

    // ---- epilogue ----
    #pragma unroll
    for (int mi = 0; mi < 2; mi++) {
        float inv0 = 1.0f / lrun[mi][0], inv1 = 1.0f / lrun[mi][1];
        int r0 = q0 + 32*w + 16*mi + g, r1 = r0 + 8;
        #pragma unroll
        for (int nt = 0; nt < 8; nt++) {
            int c = nt*8 + 2*tig;
            *(float2*)&g_o[(size_t)(b*S_LEN + r0)*HK + h*64 + c] =
                make_float2(o_acc[mi][nt][0]*inv0, o_acc[mi][nt][1]*inv0);
            *(float2*)&g_o[(size_t)(b*S_LEN + r1)*HK + h*64 + c] =
                make_float2(o_acc[mi][nt][2]*inv1, o_acc[mi][nt][3]*inv1);
        }
    }
}

// =====================================================================
extern "C" void kernel_launch(void* const* d_in, const int* in_sizes, int n_in,
                              void* d_out, int out_size)
{
    (void)in_sizes; (void)n_in; (void)out_size;
    const float* x  = (const float*)d_in[0];
    const float* Wq = (const float*)d_in[1];
    const float* bq = (const float*)d_in[2];
    const float* Wk = (const float*)d_in[3];
    const float* bk = (const float*)d_in[4];
    const float* Wv = (const float*)d_in[5];
    const float* bv = (const float*)d_in[6];
    const float* Wo = (const float*)d_in[7];
    const float* bo = (const float*)d_in[8];
    float* out = (float*)d_out;

    qkv_gemm_f16<<<dim3(HK/128, MROWS/128, 3), 128>>>(x, Wq, bq, Wk, bk, Wv, bv);

    cudaFuncSetAttribute(attn_mma, cudaFuncAttributeMaxDynamicSharedMemorySize, ATTN_SMEM);
    attn_mma<<<dim3(S_LEN/128, B_SZ*NH), 128, ATTN_SMEM>>>();

    out_gemm_f16<<<dim3(DM/128, MROWS/128), 128>>>(Wo, bo, out);
}